// round 3
// baseline (speedup 1.0000x reference)
#include <cuda_runtime.h>
#include <cstdint>
#include <cstddef>

#define BATCH 2048
#define DIN   512
#define HID   1024
#define NSTEPS 9
#define CLAMPV 100.0f

// ---------------- scratch (static __device__, no allocations) ----------------
__device__ __align__(16) float g_Z[BATCH * DIN];
__device__ __align__(16) float g_LL[BATCH];
__device__ __align__(16) float g_ZIN[BATCH * DIN];
__device__ __align__(16) float g_K[4][BATCH * DIN];
__device__ __align__(16) float g_KD[4][BATCH];
__device__ __align__(16) float g_H[(size_t)BATCH * HID];
__device__ __align__(16) float g_E[(size_t)2 * BATCH * DIN];
__device__ __align__(16) float g_UV[(size_t)2 * BATCH * 2 * HID];
__device__ __align__(16) float g_WCAT[(size_t)DIN * 2 * HID];

// ---------------- threefry2x32 (exact JAX implementation) ----------------
__host__ __device__ inline uint32_t rotl32(uint32_t x, int d) {
    return (x << d) | (x >> (32 - d));
}

__host__ __device__ inline void tfry(uint32_t k0, uint32_t k1,
                                     uint32_t c0, uint32_t c1,
                                     uint32_t& o0, uint32_t& o1) {
    uint32_t ks0 = k0, ks1 = k1, ks2 = k0 ^ k1 ^ 0x1BD11BDAu;
    uint32_t x0 = c0 + ks0, x1 = c1 + ks1;
#define TF_ROUND(rot) { x0 += x1; x1 = rotl32(x1, rot) ^ x0; }
    TF_ROUND(13) TF_ROUND(15) TF_ROUND(26) TF_ROUND(6)
    x0 += ks1; x1 += ks2 + 1u;
    TF_ROUND(17) TF_ROUND(29) TF_ROUND(16) TF_ROUND(24)
    x0 += ks2; x1 += ks0 + 2u;
    TF_ROUND(13) TF_ROUND(15) TF_ROUND(26) TF_ROUND(6)
    x0 += ks0; x1 += ks1 + 3u;
    TF_ROUND(17) TF_ROUND(29) TF_ROUND(16) TF_ROUND(24)
    x0 += ks1; x1 += ks2 + 4u;
    TF_ROUND(13) TF_ROUND(15) TF_ROUND(26) TF_ROUND(6)
    x0 += ks2; x1 += ks0 + 5u;
#undef TF_ROUND
    o0 = x0; o1 = x1;
}

// ---------------- reductions ----------------
__device__ inline float blockReduceSum(float v) {
    __shared__ float ws[8];
    int lane = threadIdx.x & 31, w = threadIdx.x >> 5;
#pragma unroll
    for (int o = 16; o > 0; o >>= 1) v += __shfl_down_sync(0xffffffffu, v, o);
    if (lane == 0) ws[w] = v;
    __syncthreads();
    if (w == 0) {
        v = (lane < ((int)blockDim.x >> 5)) ? ws[lane] : 0.f;
#pragma unroll
        for (int o = 4; o > 0; o >>= 1) v += __shfl_down_sync(0xffffffffu, v, o);
    }
    return v;  // valid on thread 0
}

// ---------------- elementwise kernels ----------------
__global__ void init_kernel(const float* __restrict__ x) {
    int i = blockIdx.x * blockDim.x + threadIdx.x;
    if (i < BATCH * DIN) g_Z[i] = x[i];
    if (i < BATCH) g_LL[i] = 0.f;
}

__global__ void build_wcat(const float* __restrict__ W1, const float* __restrict__ W2) {
    int i = blockIdx.x * blockDim.x + threadIdx.x;
    if (i >= DIN * 2 * HID) return;
    int d = i / (2 * HID);
    int c = i % (2 * HID);
    g_WCAT[i] = (c < HID) ? W1[(size_t)d * HID + c]
                          : W2[(size_t)(c - HID) * DIN + d];
}

__global__ void zin_kernel(float c1, float c2, float c3) {
    int i = blockIdx.x * blockDim.x + threadIdx.x;
    if (i >= BATCH * DIN) return;
    g_ZIN[i] = g_Z[i] + c1 * g_K[0][i] + c2 * g_K[1][i] + c3 * g_K[2][i];
}

__global__ void update_z(float dt8) {
    int i = blockIdx.x * blockDim.x + threadIdx.x;
    if (i >= BATCH * DIN) return;
    g_Z[i] += dt8 * (g_K[0][i] + 3.f * (g_K[1][i] + g_K[2][i]) + g_K[3][i]);
}

__global__ void update_ll(float dt8) {
    int b = blockIdx.x * blockDim.x + threadIdx.x;
    if (b >= BATCH) return;
    g_LL[b] += dt8 * (g_KD[0][b] + 3.f * (g_KD[1][b] + g_KD[2][b]) + g_KD[3][b]);
}

// JAX partitionable random_bits: bits[idx] = xor of both outputs of
// threefry(key, counter64 = idx)  (hi word 0, lo word idx for idx < 2^32).
// e = (bits & 1) ? +1 : -1
__global__ void gen_e_kernel(uint32_t k0a, uint32_t k1a, uint32_t k0b, uint32_t k1b) {
    int i = blockIdx.x * blockDim.x + threadIdx.x;
    if (i >= BATCH * DIN) return;
    uint32_t k0 = blockIdx.y ? k0b : k0a;
    uint32_t k1 = blockIdx.y ? k1b : k1a;
    uint32_t o0, o1;
    tfry(k0, k1, 0u, (uint32_t)i, o0, o1);
    uint32_t bits = o0 ^ o1;
    g_E[(size_t)blockIdx.y * BATCH * DIN + i] = (bits & 1u) ? 1.f : -1.f;
}

// div_est[b] = clamp( 0.5 * sum_k (1-h^2)(u1*v1 + u2*v2), +-100 );  KD[s][b] = -div_est
__global__ void div_kernel(int s) {
    int b = blockIdx.x;
    const float* h   = g_H  + (size_t)b * HID;
    const float* uv1 = g_UV + (size_t)b * 2 * HID;
    const float* uv2 = g_UV + (size_t)(b + BATCH) * 2 * HID;
    float acc = 0.f;
    for (int k = threadIdx.x; k < HID; k += blockDim.x) {
        float hh = h[k];
        float g = 1.f - hh * hh;
        acc += g * (uv1[k] * uv1[HID + k] + uv2[k] * uv2[HID + k]);
    }
    float tot = blockReduceSum(acc);
    if (threadIdx.x == 0) {
        float d = 0.5f * tot;
        d = fminf(fmaxf(d, -CLAMPV), CLAMPV);
        g_KD[s][b] = -d;
    }
}

__global__ void finalize_kernel(float* __restrict__ out) {
    int b = blockIdx.x;
    float ssum = 0.f;
    for (int d = threadIdx.x; d < DIN; d += blockDim.x) {
        float v = g_Z[(size_t)b * DIN + d];
        out[(size_t)b * DIN + d] = v;
        ssum += v * v;
    }
    float tot = blockReduceSum(ssum);
    if (threadIdx.x == 0) out[(size_t)BATCH * DIN + b] = -0.5f * tot + g_LL[b];
}

// ---------------- GEMM: double-buffered SIMT fp32 ----------------
// C(MxN) = A(MxK) @ B(KxN), all row-major. M,N,K multiples of tile dims.
// MODE 0: plain  MODE 1: tanh(acc + bias[n] + tval*tvec[n])  MODE 2: acc + bias[n]
template <int BM, int BN, int TM, int TN, int MODE>
__global__ __launch_bounds__(256, 2)
void gemm_kernel(const float* __restrict__ A, const float* __restrict__ B,
                 float* __restrict__ C, int M, int N, int K,
                 const float* __restrict__ bias, const float* __restrict__ tvec,
                 float tval) {
    constexpr int BK = 16;
    constexpr int THREADS = 256;
    constexpr int A_LD = BM * BK / 4 / THREADS;
    constexpr int B_LD = BK * BN / 4 / THREADS;
    constexpr int TX = BN / TN;

    __shared__ __align__(16) float As[2][BK][BM];
    __shared__ __align__(16) float Bs[2][BK][BN];

    const int tid = threadIdx.x;
    const int brow = blockIdx.y * BM;
    const int bcol = blockIdx.x * BN;
    const int tx = tid % TX;
    const int ty = tid / TX;

    float4 aR[A_LD], bR[B_LD];
    float acc[TM][TN];
#pragma unroll
    for (int i = 0; i < TM; i++)
#pragma unroll
        for (int j = 0; j < TN; j++) acc[i][j] = 0.f;

    // prologue: load k-tile 0 -> regs -> smem buf 0
#pragma unroll
    for (int i = 0; i < A_LD; i++) {
        int f = tid + i * THREADS; int r = f >> 2; int kc = (f & 3) << 2;
        aR[i] = *(const float4*)(A + (size_t)(brow + r) * K + kc);
    }
#pragma unroll
    for (int i = 0; i < B_LD; i++) {
        int f = tid + i * THREADS; int kr = f / (BN / 4); int nc = (f % (BN / 4)) << 2;
        bR[i] = *(const float4*)(B + (size_t)kr * N + bcol + nc);
    }
#pragma unroll
    for (int i = 0; i < A_LD; i++) {
        int f = tid + i * THREADS; int r = f >> 2; int kc = (f & 3) << 2;
        As[0][kc + 0][r] = aR[i].x; As[0][kc + 1][r] = aR[i].y;
        As[0][kc + 2][r] = aR[i].z; As[0][kc + 3][r] = aR[i].w;
    }
#pragma unroll
    for (int i = 0; i < B_LD; i++) {
        int f = tid + i * THREADS; int kr = f / (BN / 4); int nc = (f % (BN / 4)) << 2;
        *(float4*)&Bs[0][kr][nc] = bR[i];
    }
    __syncthreads();

    const int nk = K / BK;
    int buf = 0;
    for (int t = 0; t < nk; t++) {
        if (t + 1 < nk) {
            int kt = (t + 1) * BK;
#pragma unroll
            for (int i = 0; i < A_LD; i++) {
                int f = tid + i * THREADS; int r = f >> 2; int kc = (f & 3) << 2;
                aR[i] = *(const float4*)(A + (size_t)(brow + r) * K + kt + kc);
            }
#pragma unroll
            for (int i = 0; i < B_LD; i++) {
                int f = tid + i * THREADS; int kr = f / (BN / 4); int nc = (f % (BN / 4)) << 2;
                bR[i] = *(const float4*)(B + (size_t)(kt + kr) * N + bcol + nc);
            }
        }
#pragma unroll
        for (int k = 0; k < BK; k++) {
            float ra[TM], rb[TN];
#pragma unroll
            for (int i = 0; i < TM; i += 4) {
                float4 v = *(const float4*)&As[buf][k][ty * TM + i];
                ra[i] = v.x; ra[i + 1] = v.y; ra[i + 2] = v.z; ra[i + 3] = v.w;
            }
#pragma unroll
            for (int j = 0; j < TN; j += 4) {
                float4 v = *(const float4*)&Bs[buf][k][tx * TN + j];
                rb[j] = v.x; rb[j + 1] = v.y; rb[j + 2] = v.z; rb[j + 3] = v.w;
            }
#pragma unroll
            for (int i = 0; i < TM; i++)
#pragma unroll
                for (int j = 0; j < TN; j++)
                    acc[i][j] = fmaf(ra[i], rb[j], acc[i][j]);
        }
        if (t + 1 < nk) {
            int nb = buf ^ 1;
#pragma unroll
            for (int i = 0; i < A_LD; i++) {
                int f = tid + i * THREADS; int r = f >> 2; int kc = (f & 3) << 2;
                As[nb][kc + 0][r] = aR[i].x; As[nb][kc + 1][r] = aR[i].y;
                As[nb][kc + 2][r] = aR[i].z; As[nb][kc + 3][r] = aR[i].w;
            }
#pragma unroll
            for (int i = 0; i < B_LD; i++) {
                int f = tid + i * THREADS; int kr = f / (BN / 4); int nc = (f % (BN / 4)) << 2;
                *(float4*)&Bs[nb][kr][nc] = bR[i];
            }
            __syncthreads();
            buf = nb;
        }
    }

#pragma unroll
    for (int i = 0; i < TM; i++) {
        int r = brow + ty * TM + i;
#pragma unroll
        for (int j = 0; j < TN; j++) {
            int c = bcol + tx * TN + j;
            float v = acc[i][j];
            if (MODE == 1)      v = tanhf(v + bias[c] + tval * tvec[c]);
            else if (MODE == 2) v = v + bias[c];
            C[(size_t)r * N + c] = v;
        }
    }
}

// ---------------- host orchestration ----------------
extern "C" void kernel_launch(void* const* d_in, const int* in_sizes, int n_in,
                              void* d_out, int out_size) {
    (void)in_sizes; (void)n_in; (void)out_size;
    const float* x   = (const float*)d_in[0];
    const float* W1  = (const float*)d_in[1];
    const float* b1  = (const float*)d_in[2];
    const float* tw1 = (const float*)d_in[3];
    const float* W2  = (const float*)d_in[4];
    const float* b2  = (const float*)d_in[5];
    float* out = (float*)d_out;

    float *pZ, *pZIN, *pH, *pE, *pUV, *pW, *pK;
    cudaGetSymbolAddress((void**)&pZ, g_Z);
    cudaGetSymbolAddress((void**)&pZIN, g_ZIN);
    cudaGetSymbolAddress((void**)&pH, g_H);
    cudaGetSymbolAddress((void**)&pE, g_E);
    cudaGetSymbolAddress((void**)&pUV, g_UV);
    cudaGetSymbolAddress((void**)&pW, g_WCAT);
    cudaGetSymbolAddress((void**)&pK, g_K);

    init_kernel<<<(BATCH * DIN + 255) / 256, 256>>>(x);
    build_wcat<<<(DIN * 2 * HID + 255) / 256, 256>>>(W1, W2);

    // ---- JAX threefry key chain, PARTITIONABLE semantics (jax >= 0.4.30) ----
    // split(key, n) fold-like: subkey_j = threefry(key, (0, j)) full pair
    // fold_in(key, d):         threefry(key, (0, d)) full pair
    // random_bits 32-bit:      bits[idx] = out0 ^ out1 of threefry(key, (0, idx))
    uint32_t key0 = 0u, key1 = 1234u;

    for (int step = 0; step < NSTEPS; step++) {
        // key, k1k, k2k, k3k, k4k = split(key, 5)
        uint32_t nk0, nk1;
        uint32_t sk[4][2];
        tfry(key0, key1, 0u, 0u, nk0, nk1);
        for (int s = 0; s < 4; s++)
            tfry(key0, key1, 0u, (uint32_t)(s + 1), sk[s][0], sk[s][1]);
        key0 = nk0; key1 = nk1;

        double t0d = (double)step / 9.0, t1d = (double)(step + 1) / 9.0;
        float t0 = (float)t0d;
        float dt = (float)(t1d - t0d);
        float ts[4] = {t0, t0 + dt / 3.f, t0 + 2.f * dt / 3.f, (float)t1d};

        for (int s = 0; s < 4; s++) {
            const float* zin;
            if (s == 0) {
                zin = pZ;
            } else {
                float c1 = 0.f, c2 = 0.f, c3 = 0.f;
                if (s == 1)      { c1 = dt / 3.f; }
                else if (s == 2) { c1 = -dt / 3.f; c2 = dt; }
                else             { c1 = dt; c2 = -dt; c3 = dt; }
                zin_kernel<<<(BATCH * DIN + 255) / 256, 256>>>(c1, c2, c3);
                zin = pZIN;
            }
            // H = tanh(zin @ W1 + b1 + t*tw1)       [2048 x 1024, K=512]
            gemm_kernel<128, 64, 8, 4, 1>
                <<<dim3(HID / 64, BATCH / 128), 256>>>(zin, W1, pH, BATCH, HID, DIN,
                                                       b1, tw1, ts[s]);
            // K[s](z-part) = H @ W2 + b2            [2048 x 512, K=1024]
            gemm_kernel<64, 64, 4, 4, 2>
                <<<dim3(DIN / 64, BATCH / 64), 256>>>(pH, W2, pK + (size_t)s * BATCH * DIN,
                                                      BATCH, DIN, HID, b2, nullptr, 0.f);

            // randint(fold_in(k, i), shape, 0, 2) under partitionable threefry:
            //   fk = threefry(k, (0, i))
            //   k1, k2 = split(fk)  ->  k2 = threefry(fk, (0, 1))
            //   value = random_bits(k2) & 1   (span=2 -> multiplier=0 -> lower bits only)
            uint32_t keys_e[2][2];
            for (int i = 0; i < 2; i++) {
                uint32_t f0, f1;
                tfry(sk[s][0], sk[s][1], 0u, (uint32_t)i, f0, f1);   // fold_in
                tfry(f0, f1, 0u, 1u, keys_e[i][0], keys_e[i][1]);    // split -> k2
            }
            gen_e_kernel<<<dim3(BATCH * DIN / 256, 2), 256>>>(
                keys_e[0][0], keys_e[0][1], keys_e[1][0], keys_e[1][1]);

            // UV = [e1;e2] @ [W1 | W2^T]            [4096 x 2048, K=512]
            gemm_kernel<128, 128, 8, 8, 0>
                <<<dim3(2 * HID / 128, 2 * BATCH / 128), 256>>>(pE, pW, pUV,
                                                                2 * BATCH, 2 * HID, DIN,
                                                                nullptr, nullptr, 0.f);
            div_kernel<<<BATCH, 256>>>(s);
        }
        update_z<<<(BATCH * DIN + 255) / 256, 256>>>(dt * 0.125f);
        update_ll<<<(BATCH + 255) / 256, 256>>>(dt * 0.125f);
    }
    finalize_kernel<<<BATCH, 256>>>(out);
}

// round 5
// speedup vs baseline: 2.7111x; 2.7111x over previous
#include <cuda_runtime.h>
#include <cstdint>
#include <cstddef>

#define BATCH 2048
#define DIN   512
#define HID   1024
#define NSTEPS 9
#define CLAMPV 100.0f

// ---------------- scratch (static __device__, no allocations) ----------------
__device__ __align__(16) float g_Z[BATCH * DIN];
__device__ __align__(16) float g_LL[BATCH];
__device__ __align__(16) float g_ZIN[BATCH * DIN];
__device__ __align__(16) float g_K[4][BATCH * DIN];
__device__ __align__(16) float g_KD[4][BATCH];
__device__ __align__(16) float g_H[(size_t)BATCH * HID];
__device__ __align__(16) float g_E[(size_t)2 * BATCH * DIN];
__device__ __align__(16) float g_UV[(size_t)2 * BATCH * 2 * HID];
__device__ __align__(16) float g_WB3[(size_t)2 * HID * DIN];   // [W1^T ; W2]  (2048 x 512) K-major
__device__ __align__(16) float g_W2T[(size_t)DIN * HID];       // W2^T         (512 x 1024) K-major

// ---------------- threefry2x32 (exact JAX implementation) ----------------
__host__ __device__ inline uint32_t rotl32(uint32_t x, int d) {
    return (x << d) | (x >> (32 - d));
}
__host__ __device__ inline void tfry(uint32_t k0, uint32_t k1,
                                     uint32_t c0, uint32_t c1,
                                     uint32_t& o0, uint32_t& o1) {
    uint32_t ks0 = k0, ks1 = k1, ks2 = k0 ^ k1 ^ 0x1BD11BDAu;
    uint32_t x0 = c0 + ks0, x1 = c1 + ks1;
#define TF_ROUND(rot) { x0 += x1; x1 = rotl32(x1, rot) ^ x0; }
    TF_ROUND(13) TF_ROUND(15) TF_ROUND(26) TF_ROUND(6)
    x0 += ks1; x1 += ks2 + 1u;
    TF_ROUND(17) TF_ROUND(29) TF_ROUND(16) TF_ROUND(24)
    x0 += ks2; x1 += ks0 + 2u;
    TF_ROUND(13) TF_ROUND(15) TF_ROUND(26) TF_ROUND(6)
    x0 += ks0; x1 += ks1 + 3u;
    TF_ROUND(17) TF_ROUND(29) TF_ROUND(16) TF_ROUND(24)
    x0 += ks1; x1 += ks2 + 4u;
    TF_ROUND(13) TF_ROUND(15) TF_ROUND(26) TF_ROUND(6)
    x0 += ks2; x1 += ks0 + 5u;
#undef TF_ROUND
    o0 = x0; o1 = x1;
}

// ---------------- helpers ----------------
__device__ __forceinline__ float tf32r(float f) {
    uint32_t r; asm("cvt.rna.tf32.f32 %0, %1;" : "=r"(r) : "f"(f));
    return __uint_as_float(r);
}

#define MMA_TF32(d, a, b)                                                               \
    asm volatile(                                                                       \
        "mma.sync.aligned.m16n8k8.row.col.f32.tf32.tf32.f32 "                           \
        "{%0,%1,%2,%3}, {%4,%5,%6,%7}, {%8,%9}, {%0,%1,%2,%3};\n"                       \
        : "+f"((d)[0]), "+f"((d)[1]), "+f"((d)[2]), "+f"((d)[3])                        \
        : "r"((a)[0]), "r"((a)[1]), "r"((a)[2]), "r"((a)[3]), "r"((b)[0]), "r"((b)[1]))

__device__ inline float blockReduceSum(float v) {
    __shared__ float ws[8];
    int lane = threadIdx.x & 31, w = threadIdx.x >> 5;
#pragma unroll
    for (int o = 16; o > 0; o >>= 1) v += __shfl_down_sync(0xffffffffu, v, o);
    if (lane == 0) ws[w] = v;
    __syncthreads();
    if (w == 0) {
        v = (lane < ((int)blockDim.x >> 5)) ? ws[lane] : 0.f;
#pragma unroll
        for (int o = 4; o > 0; o >>= 1) v += __shfl_down_sync(0xffffffffu, v, o);
    }
    return v;
}

// ---------------- elementwise kernels ----------------
__global__ void init_kernel(const float* __restrict__ x) {
    int i = blockIdx.x * blockDim.x + threadIdx.x;
    if (i < BATCH * DIN) g_Z[i] = x[i];
    if (i < BATCH) g_LL[i] = 0.f;
}

// g_WB3 row n (K-major, K=DIN): n<HID -> W1[:,n] ; n>=HID -> W2[n-HID,:]
__global__ void build_wb3(const float* __restrict__ W1, const float* __restrict__ W2) {
    int i = blockIdx.x * blockDim.x + threadIdx.x;
    if (i >= 2 * HID * DIN) return;
    int n = i / DIN, k = i % DIN;
    g_WB3[i] = (n < HID) ? W1[(size_t)k * HID + n] : W2[(size_t)(n - HID) * DIN + k];
}
// g_W2T row n (K-major, K=HID): W2[:,n]
__global__ void build_w2t(const float* __restrict__ W2) {
    int i = blockIdx.x * blockDim.x + threadIdx.x;
    if (i >= DIN * HID) return;
    int n = i / HID, k = i % HID;
    g_W2T[i] = W2[(size_t)k * DIN + n];
}

__global__ void zin_kernel(float c1, float c2, float c3) {
    int i = blockIdx.x * blockDim.x + threadIdx.x;
    if (i >= BATCH * DIN) return;
    g_ZIN[i] = g_Z[i] + c1 * g_K[0][i] + c2 * g_K[1][i] + c3 * g_K[2][i];
}

__global__ void update_z(float dt8) {
    int i = blockIdx.x * blockDim.x + threadIdx.x;
    if (i >= BATCH * DIN) return;
    g_Z[i] += dt8 * (g_K[0][i] + 3.f * (g_K[1][i] + g_K[2][i]) + g_K[3][i]);
}

__global__ void update_ll(float dt8) {
    int b = blockIdx.x * blockDim.x + threadIdx.x;
    if (b >= BATCH) return;
    g_LL[b] += dt8 * (g_KD[0][b] + 3.f * (g_KD[1][b] + g_KD[2][b]) + g_KD[3][b]);
}

// JAX partitionable random_bits: bits[idx] = xor of outputs of threefry(key, (0, idx))
__global__ void gen_e_kernel(uint32_t k0a, uint32_t k1a, uint32_t k0b, uint32_t k1b) {
    int i = blockIdx.x * blockDim.x + threadIdx.x;
    if (i >= BATCH * DIN) return;
    uint32_t k0 = blockIdx.y ? k0b : k0a;
    uint32_t k1 = blockIdx.y ? k1b : k1a;
    uint32_t o0, o1;
    tfry(k0, k1, 0u, (uint32_t)i, o0, o1);
    g_E[(size_t)blockIdx.y * BATCH * DIN + i] = ((o0 ^ o1) & 1u) ? 1.f : -1.f;
}

__global__ void div_kernel(int s) {
    int b = blockIdx.x;
    const float* h   = g_H  + (size_t)b * HID;
    const float* uv1 = g_UV + (size_t)b * 2 * HID;
    const float* uv2 = g_UV + (size_t)(b + BATCH) * 2 * HID;
    float acc = 0.f;
    for (int k = threadIdx.x; k < HID; k += blockDim.x) {
        float hh = h[k];
        float g = 1.f - hh * hh;
        acc += g * (uv1[k] * uv1[HID + k] + uv2[k] * uv2[HID + k]);
    }
    float tot = blockReduceSum(acc);
    if (threadIdx.x == 0) {
        float d = 0.5f * tot;
        d = fminf(fmaxf(d, -CLAMPV), CLAMPV);
        g_KD[s][b] = -d;
    }
}

__global__ void finalize_kernel(float* __restrict__ out) {
    int b = blockIdx.x;
    float ssum = 0.f;
    for (int d = threadIdx.x; d < DIN; d += blockDim.x) {
        float v = g_Z[(size_t)b * DIN + d];
        out[(size_t)b * DIN + d] = v;
        ssum += v * v;
    }
    float tot = blockReduceSum(ssum);
    if (threadIdx.x == 0) out[(size_t)BATCH * DIN + b] = -0.5f * tot + g_LL[b];
}

// ---------------- tf32 mma.sync GEMM ----------------
// C[M,N] = A[M,K] @ Brows[N,K]^T.  A row-major, B stored K-major per output column
// (exactly the .col operand layout).  BK=32 floats.  Double-buffered smem, XOR swizzle.
// MODE 0: raw   MODE 1: tanh(acc + bias + tval*tvec)   MODE 2: acc + bias
template <int BM, int BN, int WM, int WN, int MODE>
__global__ __launch_bounds__((BM / WM) * (BN / WN) * 32, 1)
void gemm_mma(const float* __restrict__ A, const float* __restrict__ B,
              float* __restrict__ C, int M, int N, int K,
              const float* __restrict__ bias, const float* __restrict__ tvec, float tval) {
    extern __shared__ __align__(16) char smem[];
    constexpr int THREADS = (BM / WM) * (BN / WN) * 32;
    constexpr int WCOLS = BN / WN;
    constexpr int MT = WM / 16, NT = WN / 8;
    constexpr int A4 = BM * 8 / THREADS;  // float4 loads per thread for A tile (BM x 32)
    constexpr int B4 = BN * 8 / THREADS;

    float* sbias = (float*)smem;
    float* sA = (float*)(smem + 1024);
    float* sB = sA + 2 * BM * 32;

    const int tid = threadIdx.x;
    const int lane = tid & 31;
    const int warp = tid >> 5;
    const int g = lane >> 2;    // 0..7
    const int tg = lane & 3;    // 0..3
    const int sw = g * 4;       // swizzle term (rows within a tile: r&7 == g)
    const int wrow = (warp / WCOLS) * WM;
    const int wcol = (warp % WCOLS) * WN;
    const int brow = blockIdx.y * BM;
    const int bcol = blockIdx.x * BN;

    if (MODE == 1 && tid < BN) sbias[tid] = bias[bcol + tid] + tval * tvec[bcol + tid];
    if (MODE == 2 && tid < BN) sbias[tid] = bias[bcol + tid];

    float acc[MT][NT][4];
#pragma unroll
    for (int i = 0; i < MT; i++)
#pragma unroll
        for (int j = 0; j < NT; j++)
#pragma unroll
            for (int q = 0; q < 4; q++) acc[i][j][q] = 0.f;

    float4 aR[A4], bR[B4];
    // prologue: k-tile 0 -> regs
#pragma unroll
    for (int i = 0; i < A4; i++) {
        int f = tid + i * THREADS; int r = f >> 3, seg = f & 7;
        aR[i] = *(const float4*)(A + (size_t)(brow + r) * K + seg * 4);
    }
#pragma unroll
    for (int i = 0; i < B4; i++) {
        int f = tid + i * THREADS; int r = f >> 3, seg = f & 7;
        bR[i] = *(const float4*)(B + (size_t)(bcol + r) * K + seg * 4);
    }
    // -> smem buf 0 (tf32 convert + swizzle)
#pragma unroll
    for (int i = 0; i < A4; i++) {
        int f = tid + i * THREADS; int r = f >> 3, seg = f & 7;
        int o = r * 32 + ((seg * 4) ^ ((r & 7) * 4));
        float4 w;
        w.x = tf32r(aR[i].x); w.y = tf32r(aR[i].y); w.z = tf32r(aR[i].z); w.w = tf32r(aR[i].w);
        *(float4*)(sA + o) = w;
    }
#pragma unroll
    for (int i = 0; i < B4; i++) {
        int f = tid + i * THREADS; int r = f >> 3, seg = f & 7;
        int o = r * 32 + ((seg * 4) ^ ((r & 7) * 4));
        float4 w;
        w.x = tf32r(bR[i].x); w.y = tf32r(bR[i].y); w.z = tf32r(bR[i].z); w.w = tf32r(bR[i].w);
        *(float4*)(sB + o) = w;
    }
    __syncthreads();

    const int nk = K >> 5;
    for (int t = 0; t < nk; t++) {
        const int buf = t & 1;
        if (t + 1 < nk) {
            const int kt = (t + 1) << 5;
#pragma unroll
            for (int i = 0; i < A4; i++) {
                int f = tid + i * THREADS; int r = f >> 3, seg = f & 7;
                aR[i] = *(const float4*)(A + (size_t)(brow + r) * K + kt + seg * 4);
            }
#pragma unroll
            for (int i = 0; i < B4; i++) {
                int f = tid + i * THREADS; int r = f >> 3, seg = f & 7;
                bR[i] = *(const float4*)(B + (size_t)(bcol + r) * K + kt + seg * 4);
            }
        }
        const float* sa = sA + buf * BM * 32;
        const float* sb = sB + buf * BN * 32;
#pragma unroll
        for (int ks = 0; ks < 4; ks++) {
            const int c0 = ks * 8 + tg;
            const int c1 = c0 + 4;
            uint32_t af[MT][4], bf[NT][2];
#pragma unroll
            for (int mt = 0; mt < MT; mt++) {
                int r0 = wrow + mt * 16 + g;
                int r1 = r0 + 8;
                af[mt][0] = __float_as_uint(sa[r0 * 32 + (c0 ^ sw)]);
                af[mt][1] = __float_as_uint(sa[r1 * 32 + (c0 ^ sw)]);
                af[mt][2] = __float_as_uint(sa[r0 * 32 + (c1 ^ sw)]);
                af[mt][3] = __float_as_uint(sa[r1 * 32 + (c1 ^ sw)]);
            }
#pragma unroll
            for (int nt = 0; nt < NT; nt++) {
                int n0 = wcol + nt * 8 + g;
                bf[nt][0] = __float_as_uint(sb[n0 * 32 + (c0 ^ sw)]);
                bf[nt][1] = __float_as_uint(sb[n0 * 32 + (c1 ^ sw)]);
            }
#pragma unroll
            for (int mt = 0; mt < MT; mt++)
#pragma unroll
                for (int nt = 0; nt < NT; nt++)
                    MMA_TF32(acc[mt][nt], af[mt], bf[nt]);
        }
        if (t + 1 < nk) {
            const int nb = buf ^ 1;
            float* dA = sA + nb * BM * 32;
            float* dB = sB + nb * BN * 32;
#pragma unroll
            for (int i = 0; i < A4; i++) {
                int f = tid + i * THREADS; int r = f >> 3, seg = f & 7;
                int o = r * 32 + ((seg * 4) ^ ((r & 7) * 4));
                float4 w;
                w.x = tf32r(aR[i].x); w.y = tf32r(aR[i].y); w.z = tf32r(aR[i].z); w.w = tf32r(aR[i].w);
                *(float4*)(dA + o) = w;
            }
#pragma unroll
            for (int i = 0; i < B4; i++) {
                int f = tid + i * THREADS; int r = f >> 3, seg = f & 7;
                int o = r * 32 + ((seg * 4) ^ ((r & 7) * 4));
                float4 w;
                w.x = tf32r(bR[i].x); w.y = tf32r(bR[i].y); w.z = tf32r(bR[i].z); w.w = tf32r(bR[i].w);
                *(float4*)(dB + o) = w;
            }
            __syncthreads();
        }
    }

    // epilogue: c0,c1 at (row g, col 2*tg / +1), c2,c3 at row g+8
#pragma unroll
    for (int mt = 0; mt < MT; mt++) {
#pragma unroll
        for (int nt = 0; nt < NT; nt++) {
            int lc = wcol + nt * 8 + tg * 2;
            int r0 = brow + wrow + mt * 16 + g;
            float v0 = acc[mt][nt][0], v1 = acc[mt][nt][1];
            float v2 = acc[mt][nt][2], v3 = acc[mt][nt][3];
            if (MODE == 1) {
                float b0 = sbias[lc], b1 = sbias[lc + 1];
                v0 = tanhf(v0 + b0); v1 = tanhf(v1 + b1);
                v2 = tanhf(v2 + b0); v3 = tanhf(v3 + b1);
            } else if (MODE == 2) {
                float b0 = sbias[lc], b1 = sbias[lc + 1];
                v0 += b0; v1 += b1; v2 += b0; v3 += b1;
            }
            *(float2*)(C + (size_t)r0 * N + bcol + lc)       = make_float2(v0, v1);
            *(float2*)(C + (size_t)(r0 + 8) * N + bcol + lc) = make_float2(v2, v3);
        }
    }
}

// ---------------- host orchestration ----------------
extern "C" void kernel_launch(void* const* d_in, const int* in_sizes, int n_in,
                              void* d_out, int out_size) {
    (void)in_sizes; (void)n_in; (void)out_size;
    const float* x   = (const float*)d_in[0];
    const float* W1  = (const float*)d_in[1];
    const float* b1  = (const float*)d_in[2];
    const float* tw1 = (const float*)d_in[3];
    const float* W2  = (const float*)d_in[4];
    const float* b2  = (const float*)d_in[5];
    float* out = (float*)d_out;

    float *pZ, *pZIN, *pH, *pE, *pUV, *pWB3, *pW2T, *pK;
    cudaGetSymbolAddress((void**)&pZ, g_Z);
    cudaGetSymbolAddress((void**)&pZIN, g_ZIN);
    cudaGetSymbolAddress((void**)&pH, g_H);
    cudaGetSymbolAddress((void**)&pE, g_E);
    cudaGetSymbolAddress((void**)&pUV, g_UV);
    cudaGetSymbolAddress((void**)&pWB3, g_WB3);
    cudaGetSymbolAddress((void**)&pW2T, g_W2T);
    cudaGetSymbolAddress((void**)&pK, g_K);

    const int SM_BIG = 1024 + 2 * 128 * 32 * 4 + 2 * 128 * 32 * 4;  // 66560
    const int SM_G2  = 1024 + 2 * 64 * 32 * 4 + 2 * 128 * 32 * 4;   // 50176
    cudaFuncSetAttribute((const void*)gemm_mma<128, 128, 64, 32, 1>,
                         cudaFuncAttributeMaxDynamicSharedMemorySize, SM_BIG);
    cudaFuncSetAttribute((const void*)gemm_mma<64, 128, 32, 32, 2>,
                         cudaFuncAttributeMaxDynamicSharedMemorySize, SM_G2);
    cudaFuncSetAttribute((const void*)gemm_mma<128, 128, 64, 32, 0>,
                         cudaFuncAttributeMaxDynamicSharedMemorySize, SM_BIG);

    init_kernel<<<(BATCH * DIN + 255) / 256, 256>>>(x);
    build_wb3<<<(2 * HID * DIN + 255) / 256, 256>>>(W1, W2);
    build_w2t<<<(DIN * HID + 255) / 256, 256>>>(W2);

    // JAX threefry, partitionable semantics
    uint32_t key0 = 0u, key1 = 1234u;

    for (int step = 0; step < NSTEPS; step++) {
        uint32_t nk0, nk1;
        uint32_t sk[4][2];
        tfry(key0, key1, 0u, 0u, nk0, nk1);
        for (int s = 0; s < 4; s++)
            tfry(key0, key1, 0u, (uint32_t)(s + 1), sk[s][0], sk[s][1]);
        key0 = nk0; key1 = nk1;

        double t0d = (double)step / 9.0, t1d = (double)(step + 1) / 9.0;
        float t0 = (float)t0d;
        float dt = (float)(t1d - t0d);
        float ts[4] = {t0, t0 + dt / 3.f, t0 + 2.f * dt / 3.f, (float)t1d};

        for (int s = 0; s < 4; s++) {
            const float* zin;
            if (s == 0) {
                zin = pZ;
            } else {
                float c1 = 0.f, c2 = 0.f, c3 = 0.f;
                if (s == 1)      { c1 = dt / 3.f; }
                else if (s == 2) { c1 = -dt / 3.f; c2 = dt; }
                else             { c1 = dt; c2 = -dt; c3 = dt; }
                zin_kernel<<<(BATCH * DIN + 255) / 256, 256>>>(c1, c2, c3);
                zin = pZIN;
            }
            // H = tanh(zin @ W1 + b1 + t*tw1)   [2048x1024, K=512]
            gemm_mma<128, 128, 64, 32, 1><<<dim3(HID / 128, BATCH / 128), 256, SM_BIG>>>(
                zin, pWB3, pH, BATCH, HID, DIN, b1, tw1, ts[s]);
            // K[s] = H @ W2 + b2                [2048x512, K=1024]
            gemm_mma<64, 128, 32, 32, 2><<<dim3(DIN / 128, BATCH / 64), 256, SM_G2>>>(
                pH, pW2T, pK + (size_t)s * BATCH * DIN, BATCH, DIN, HID, b2, nullptr, 0.f);

            // e keys: fk = tfry(k,(0,i)); k2 = tfry(fk,(0,1)); bits = xor-halves & 1
            uint32_t keys_e[2][2];
            for (int i = 0; i < 2; i++) {
                uint32_t f0, f1;
                tfry(sk[s][0], sk[s][1], 0u, (uint32_t)i, f0, f1);
                tfry(f0, f1, 0u, 1u, keys_e[i][0], keys_e[i][1]);
            }
            gen_e_kernel<<<dim3(BATCH * DIN / 256, 2), 256>>>(
                keys_e[0][0], keys_e[0][1], keys_e[1][0], keys_e[1][1]);

            // UV = [e1;e2] @ [W1 | W2^T]        [4096x2048, K=512]
            gemm_mma<128, 128, 64, 32, 0><<<dim3(2 * HID / 128, 2 * BATCH / 128), 256, SM_BIG>>>(
                pE, pWB3, pUV, 2 * BATCH, 2 * HID, DIN, nullptr, nullptr, 0.f);
            div_kernel<<<BATCH, 256>>>(s);
        }
        update_z<<<(BATCH * DIN + 255) / 256, 256>>>(dt * 0.125f);
        update_ll<<<(BATCH + 255) / 256, 256>>>(dt * 0.125f);
    }
    finalize_kernel<<<BATCH, 256>>>(out);
}

// round 6
// speedup vs baseline: 3.0301x; 1.1176x over previous
#include <cuda_runtime.h>
#include <cstdint>
#include <cstddef>

#define BATCH 2048
#define DIN   512
#define HID   1024
#define NSTEPS 9
#define CLAMPV 100.0f

// ---------------- scratch (static __device__, no allocations) ----------------
__device__ __align__(16) float g_Z[BATCH * DIN];
__device__ __align__(16) float g_LL[BATCH];
__device__ __align__(16) float g_ZIN[BATCH * DIN];
__device__ __align__(16) float g_K[4][BATCH * DIN];
__device__ __align__(16) float g_KD[4][BATCH];
__device__ __align__(16) float g_H[(size_t)BATCH * HID];
__device__ __align__(16) float g_E[(size_t)2 * BATCH * DIN];
__device__ __align__(16) float g_UV[(size_t)2 * BATCH * 2 * HID];
__device__ __align__(16) float g_WB3[(size_t)2 * HID * DIN];   // [W1^T ; W2]  (2048 x 512) K-major
__device__ __align__(16) float g_W2T[(size_t)DIN * HID];       // W2^T         (512 x 1024) K-major

// ---------------- threefry2x32 (exact JAX implementation) ----------------
__host__ __device__ inline uint32_t rotl32(uint32_t x, int d) {
    return (x << d) | (x >> (32 - d));
}
__host__ __device__ inline void tfry(uint32_t k0, uint32_t k1,
                                     uint32_t c0, uint32_t c1,
                                     uint32_t& o0, uint32_t& o1) {
    uint32_t ks0 = k0, ks1 = k1, ks2 = k0 ^ k1 ^ 0x1BD11BDAu;
    uint32_t x0 = c0 + ks0, x1 = c1 + ks1;
#define TF_ROUND(rot) { x0 += x1; x1 = rotl32(x1, rot) ^ x0; }
    TF_ROUND(13) TF_ROUND(15) TF_ROUND(26) TF_ROUND(6)
    x0 += ks1; x1 += ks2 + 1u;
    TF_ROUND(17) TF_ROUND(29) TF_ROUND(16) TF_ROUND(24)
    x0 += ks2; x1 += ks0 + 2u;
    TF_ROUND(13) TF_ROUND(15) TF_ROUND(26) TF_ROUND(6)
    x0 += ks0; x1 += ks1 + 3u;
    TF_ROUND(17) TF_ROUND(29) TF_ROUND(16) TF_ROUND(24)
    x0 += ks1; x1 += ks2 + 4u;
    TF_ROUND(13) TF_ROUND(15) TF_ROUND(26) TF_ROUND(6)
    x0 += ks2; x1 += ks0 + 5u;
#undef TF_ROUND
    o0 = x0; o1 = x1;
}

// ---------------- helpers ----------------
__device__ __forceinline__ float tf32r(float f) {
    uint32_t r; asm("cvt.rna.tf32.f32 %0, %1;" : "=r"(r) : "f"(f));
    return __uint_as_float(r);
}

#define MMA_TF32(d, a, b)                                                               \
    asm volatile(                                                                       \
        "mma.sync.aligned.m16n8k8.row.col.f32.tf32.tf32.f32 "                           \
        "{%0,%1,%2,%3}, {%4,%5,%6,%7}, {%8,%9}, {%0,%1,%2,%3};\n"                       \
        : "+f"((d)[0]), "+f"((d)[1]), "+f"((d)[2]), "+f"((d)[3])                        \
        : "r"((a)[0]), "r"((a)[1]), "r"((a)[2]), "r"((a)[3]), "r"((b)[0]), "r"((b)[1]))

#define LDMX4(r0, r1, r2, r3, addr)                                                     \
    asm volatile("ldmatrix.sync.aligned.m8n8.x4.shared.b16 {%0,%1,%2,%3}, [%4];"        \
                 : "=r"(r0), "=r"(r1), "=r"(r2), "=r"(r3) : "r"(addr))

__device__ inline float blockReduceSum(float v) {
    __shared__ float ws[8];
    int lane = threadIdx.x & 31, w = threadIdx.x >> 5;
#pragma unroll
    for (int o = 16; o > 0; o >>= 1) v += __shfl_down_sync(0xffffffffu, v, o);
    if (lane == 0) ws[w] = v;
    __syncthreads();
    if (w == 0) {
        v = (lane < ((int)blockDim.x >> 5)) ? ws[lane] : 0.f;
#pragma unroll
        for (int o = 4; o > 0; o >>= 1) v += __shfl_down_sync(0xffffffffu, v, o);
    }
    return v;
}

// ---------------- elementwise kernels ----------------
__global__ void init_kernel(const float* __restrict__ x) {
    int i = blockIdx.x * blockDim.x + threadIdx.x;
    if (i < BATCH * DIN) g_Z[i] = x[i];
    if (i < BATCH) g_LL[i] = 0.f;
}

// g_WB3 row n (K-major, K=DIN): n<HID -> W1[:,n] ; n>=HID -> W2[n-HID,:]
__global__ void build_wb3(const float* __restrict__ W1, const float* __restrict__ W2) {
    int i = blockIdx.x * blockDim.x + threadIdx.x;
    if (i >= 2 * HID * DIN) return;
    int n = i / DIN, k = i % DIN;
    g_WB3[i] = (n < HID) ? W1[(size_t)k * HID + n] : W2[(size_t)(n - HID) * DIN + k];
}
// g_W2T row n (K-major, K=HID): W2[:,n]
__global__ void build_w2t(const float* __restrict__ W2) {
    int i = blockIdx.x * blockDim.x + threadIdx.x;
    if (i >= DIN * HID) return;
    int n = i / HID, k = i % HID;
    g_W2T[i] = W2[(size_t)k * DIN + n];
}

__global__ void zin_kernel(float c1, float c2, float c3) {
    int i = blockIdx.x * blockDim.x + threadIdx.x;
    if (i >= BATCH * DIN) return;
    g_ZIN[i] = g_Z[i] + c1 * g_K[0][i] + c2 * g_K[1][i] + c3 * g_K[2][i];
}

__global__ void update_z(float dt8) {
    int i = blockIdx.x * blockDim.x + threadIdx.x;
    if (i >= BATCH * DIN) return;
    g_Z[i] += dt8 * (g_K[0][i] + 3.f * (g_K[1][i] + g_K[2][i]) + g_K[3][i]);
}

__global__ void update_ll(float dt8) {
    int b = blockIdx.x * blockDim.x + threadIdx.x;
    if (b >= BATCH) return;
    g_LL[b] += dt8 * (g_KD[0][b] + 3.f * (g_KD[1][b] + g_KD[2][b]) + g_KD[3][b]);
}

// JAX partitionable random_bits: bits[idx] = xor of outputs of threefry(key, (0, idx))
__global__ void gen_e_kernel(uint32_t k0a, uint32_t k1a, uint32_t k0b, uint32_t k1b) {
    int i = blockIdx.x * blockDim.x + threadIdx.x;
    if (i >= BATCH * DIN) return;
    uint32_t k0 = blockIdx.y ? k0b : k0a;
    uint32_t k1 = blockIdx.y ? k1b : k1a;
    uint32_t o0, o1;
    tfry(k0, k1, 0u, (uint32_t)i, o0, o1);
    g_E[(size_t)blockIdx.y * BATCH * DIN + i] = ((o0 ^ o1) & 1u) ? 1.f : -1.f;
}

__global__ void div_kernel(int s) {
    int b = blockIdx.x;
    const float* h   = g_H  + (size_t)b * HID;
    const float* uv1 = g_UV + (size_t)b * 2 * HID;
    const float* uv2 = g_UV + (size_t)(b + BATCH) * 2 * HID;
    float acc = 0.f;
    for (int k = threadIdx.x; k < HID; k += blockDim.x) {
        float hh = h[k];
        float g = 1.f - hh * hh;
        acc += g * (uv1[k] * uv1[HID + k] + uv2[k] * uv2[HID + k]);
    }
    float tot = blockReduceSum(acc);
    if (threadIdx.x == 0) {
        float d = 0.5f * tot;
        d = fminf(fmaxf(d, -CLAMPV), CLAMPV);
        g_KD[s][b] = -d;
    }
}

__global__ void finalize_kernel(float* __restrict__ out) {
    int b = blockIdx.x;
    float ssum = 0.f;
    for (int d = threadIdx.x; d < DIN; d += blockDim.x) {
        float v = g_Z[(size_t)b * DIN + d];
        out[(size_t)b * DIN + d] = v;
        ssum += v * v;
    }
    float tot = blockReduceSum(ssum);
    if (threadIdx.x == 0) out[(size_t)BATCH * DIN + b] = -0.5f * tot + g_LL[b];
}

// ---------------- tf32 mma.sync GEMM, ldmatrix fragments, 32x32 warp tile ----
// C[M,N] = A[M,K] @ Brows[N,K]^T.  A row-major; B stored K-major per output column.
// BK=32 floats.  Double-buffered smem, 16B XOR swizzle.  Warp tile 32x32.
// MODE 0: raw   MODE 1: tanh(acc + bias + tval*tvec)   MODE 2: acc + bias
template <int BM, int BN, int MODE>
__global__ __launch_bounds__((BM / 32) * (BN / 32) * 32, 512 / ((BM / 32) * (BN / 32) * 32))
void gemm_mma(const float* __restrict__ A, const float* __restrict__ B,
              float* __restrict__ C, int M, int N, int K,
              const float* __restrict__ bias, const float* __restrict__ tvec, float tval) {
    extern __shared__ __align__(16) char smem[];
    constexpr int THREADS = (BM / 32) * (BN / 32) * 32;
    constexpr int WCOLS = BN / 32;
    constexpr int A4 = BM * 8 / THREADS;   // float4 loads per thread (tile BM x 32)
    constexpr int B4 = BN * 8 / THREADS;

    float* sbias = (float*)smem;
    float* sA = (float*)(smem + 1024);
    float* sB = sA + 2 * BM * 32;

    const int tid = threadIdx.x;
    const int lane = tid & 31;
    const int warp = tid >> 5;
    const int g = lane >> 2;     // 0..7
    const int tg = lane & 3;     // 0..3
    const int wrow = (warp / WCOLS) * 32;
    const int wcol = (warp % WCOLS) * 32;
    const int brow = blockIdx.y * BM;
    const int bcol = blockIdx.x * BN;

    const uint32_t sA_u = (uint32_t)__cvta_generic_to_shared(sA);
    const uint32_t sB_u = (uint32_t)__cvta_generic_to_shared(sB);

    if (MODE == 1 && tid < BN) sbias[tid] = bias[bcol + tid] + tval * tvec[bcol + tid];
    if (MODE == 2 && tid < BN) sbias[tid] = bias[bcol + tid];

    float acc[2][4][4];
#pragma unroll
    for (int i = 0; i < 2; i++)
#pragma unroll
        for (int j = 0; j < 4; j++)
#pragma unroll
            for (int q = 0; q < 4; q++) acc[i][j][q] = 0.f;

    // ldmatrix per-lane row/chunk bases (chunk = 16B unit within 32-float row)
    const int rA_l = wrow + (lane & 15);          // + mt*16
    const int cA_l = lane >> 4;                    // + ks*2
    const int rB_l = wcol + ((lane >> 4) * 8) + (lane & 7);  // + p*16
    const int cB_l = (lane >> 3) & 1;              // + ks*2

    float4 aR[A4], bR[B4];
    // prologue: k-tile 0 -> regs
#pragma unroll
    for (int i = 0; i < A4; i++) {
        int f = tid + i * THREADS; int r = f >> 3, seg = f & 7;
        aR[i] = *(const float4*)(A + (size_t)(brow + r) * K + seg * 4);
    }
#pragma unroll
    for (int i = 0; i < B4; i++) {
        int f = tid + i * THREADS; int r = f >> 3, seg = f & 7;
        bR[i] = *(const float4*)(B + (size_t)(bcol + r) * K + seg * 4);
    }
    // -> smem buf 0 (tf32 convert + swizzle)
#pragma unroll
    for (int i = 0; i < A4; i++) {
        int f = tid + i * THREADS; int r = f >> 3, seg = f & 7;
        int o = r * 32 + ((seg * 4) ^ ((r & 7) * 4));
        float4 w;
        w.x = tf32r(aR[i].x); w.y = tf32r(aR[i].y); w.z = tf32r(aR[i].z); w.w = tf32r(aR[i].w);
        *(float4*)(sA + o) = w;
    }
#pragma unroll
    for (int i = 0; i < B4; i++) {
        int f = tid + i * THREADS; int r = f >> 3, seg = f & 7;
        int o = r * 32 + ((seg * 4) ^ ((r & 7) * 4));
        float4 w;
        w.x = tf32r(bR[i].x); w.y = tf32r(bR[i].y); w.z = tf32r(bR[i].z); w.w = tf32r(bR[i].w);
        *(float4*)(sB + o) = w;
    }
    __syncthreads();

    const int nk = K >> 5;
    for (int t = 0; t < nk; t++) {
        const int buf = t & 1;
        if (t + 1 < nk) {
            const int kt = (t + 1) << 5;
#pragma unroll
            for (int i = 0; i < A4; i++) {
                int f = tid + i * THREADS; int r = f >> 3, seg = f & 7;
                aR[i] = *(const float4*)(A + (size_t)(brow + r) * K + kt + seg * 4);
            }
#pragma unroll
            for (int i = 0; i < B4; i++) {
                int f = tid + i * THREADS; int r = f >> 3, seg = f & 7;
                bR[i] = *(const float4*)(B + (size_t)(bcol + r) * K + kt + seg * 4);
            }
        }
        const uint32_t sa_u = sA_u + buf * (BM * 32 * 4);
        const uint32_t sb_u = sB_u + buf * (BN * 32 * 4);
#pragma unroll
        for (int ks = 0; ks < 4; ks++) {
            uint32_t af[2][4], bf[4][2];
#pragma unroll
            for (int mt = 0; mt < 2; mt++) {
                int r = rA_l + mt * 16;
                int ch = ks * 2 + cA_l;
                uint32_t addr = sa_u + (r * 32 + ((ch * 4) ^ ((r & 7) * 4))) * 4;
                LDMX4(af[mt][0], af[mt][1], af[mt][2], af[mt][3], addr);
            }
#pragma unroll
            for (int p = 0; p < 2; p++) {
                int r = rB_l + p * 16;
                int ch = ks * 2 + cB_l;
                uint32_t addr = sb_u + (r * 32 + ((ch * 4) ^ ((r & 7) * 4))) * 4;
                LDMX4(bf[2 * p][0], bf[2 * p][1], bf[2 * p + 1][0], bf[2 * p + 1][1], addr);
            }
#pragma unroll
            for (int mt = 0; mt < 2; mt++)
#pragma unroll
                for (int nt = 0; nt < 4; nt++)
                    MMA_TF32(acc[mt][nt], af[mt], bf[nt]);
        }
        if (t + 1 < nk) {
            const int nb = buf ^ 1;
            float* dA = sA + nb * BM * 32;
            float* dB = sB + nb * BN * 32;
            __syncthreads();
#pragma unroll
            for (int i = 0; i < A4; i++) {
                int f = tid + i * THREADS; int r = f >> 3, seg = f & 7;
                int o = r * 32 + ((seg * 4) ^ ((r & 7) * 4));
                float4 w;
                w.x = tf32r(aR[i].x); w.y = tf32r(aR[i].y); w.z = tf32r(aR[i].z); w.w = tf32r(aR[i].w);
                *(float4*)(dA + o) = w;
            }
#pragma unroll
            for (int i = 0; i < B4; i++) {
                int f = tid + i * THREADS; int r = f >> 3, seg = f & 7;
                int o = r * 32 + ((seg * 4) ^ ((r & 7) * 4));
                float4 w;
                w.x = tf32r(bR[i].x); w.y = tf32r(bR[i].y); w.z = tf32r(bR[i].z); w.w = tf32r(bR[i].w);
                *(float4*)(dB + o) = w;
            }
            __syncthreads();
        }
    }

    // epilogue
#pragma unroll
    for (int mt = 0; mt < 2; mt++) {
#pragma unroll
        for (int nt = 0; nt < 4; nt++) {
            int lc = wcol + nt * 8 + tg * 2;
            int r0 = brow + wrow + mt * 16 + g;
            float v0 = acc[mt][nt][0], v1 = acc[mt][nt][1];
            float v2 = acc[mt][nt][2], v3 = acc[mt][nt][3];
            if (MODE == 1) {
                float b0 = sbias[lc], b1 = sbias[lc + 1];
                v0 = tanhf(v0 + b0); v1 = tanhf(v1 + b1);
                v2 = tanhf(v2 + b0); v3 = tanhf(v3 + b1);
            } else if (MODE == 2) {
                float b0 = sbias[lc], b1 = sbias[lc + 1];
                v0 += b0; v1 += b1; v2 += b0; v3 += b1;
            }
            *(float2*)(C + (size_t)r0 * N + bcol + lc)       = make_float2(v0, v1);
            *(float2*)(C + (size_t)(r0 + 8) * N + bcol + lc) = make_float2(v2, v3);
        }
    }
}

// ---------------- host orchestration ----------------
extern "C" void kernel_launch(void* const* d_in, const int* in_sizes, int n_in,
                              void* d_out, int out_size) {
    (void)in_sizes; (void)n_in; (void)out_size;
    const float* x   = (const float*)d_in[0];
    const float* W1  = (const float*)d_in[1];
    const float* b1  = (const float*)d_in[2];
    const float* tw1 = (const float*)d_in[3];
    const float* W2  = (const float*)d_in[4];
    const float* b2  = (const float*)d_in[5];
    float* out = (float*)d_out;

    float *pZ, *pZIN, *pH, *pE, *pUV, *pWB3, *pW2T, *pK;
    cudaGetSymbolAddress((void**)&pZ, g_Z);
    cudaGetSymbolAddress((void**)&pZIN, g_ZIN);
    cudaGetSymbolAddress((void**)&pH, g_H);
    cudaGetSymbolAddress((void**)&pE, g_E);
    cudaGetSymbolAddress((void**)&pUV, g_UV);
    cudaGetSymbolAddress((void**)&pWB3, g_WB3);
    cudaGetSymbolAddress((void**)&pW2T, g_W2T);
    cudaGetSymbolAddress((void**)&pK, g_K);

    const int SM_BIG = 1024 + 2 * (128 + 64) * 32 * 4;  // 50176  (128x64 tiles)
    const int SM_G2  = 1024 + 2 * (64 + 64) * 32 * 4;   // 33792  (64x64 tiles)
    cudaFuncSetAttribute((const void*)gemm_mma<128, 64, 1>,
                         cudaFuncAttributeMaxDynamicSharedMemorySize, SM_BIG);
    cudaFuncSetAttribute((const void*)gemm_mma<64, 64, 2>,
                         cudaFuncAttributeMaxDynamicSharedMemorySize, SM_G2);
    cudaFuncSetAttribute((const void*)gemm_mma<128, 64, 0>,
                         cudaFuncAttributeMaxDynamicSharedMemorySize, SM_BIG);

    init_kernel<<<(BATCH * DIN + 255) / 256, 256>>>(x);
    build_wb3<<<(2 * HID * DIN + 255) / 256, 256>>>(W1, W2);
    build_w2t<<<(DIN * HID + 255) / 256, 256>>>(W2);

    // JAX threefry, partitionable semantics
    uint32_t key0 = 0u, key1 = 1234u;

    for (int step = 0; step < NSTEPS; step++) {
        uint32_t nk0, nk1;
        uint32_t sk[4][2];
        tfry(key0, key1, 0u, 0u, nk0, nk1);
        for (int s = 0; s < 4; s++)
            tfry(key0, key1, 0u, (uint32_t)(s + 1), sk[s][0], sk[s][1]);
        key0 = nk0; key1 = nk1;

        double t0d = (double)step / 9.0, t1d = (double)(step + 1) / 9.0;
        float t0 = (float)t0d;
        float dt = (float)(t1d - t0d);
        float ts[4] = {t0, t0 + dt / 3.f, t0 + 2.f * dt / 3.f, (float)t1d};

        for (int s = 0; s < 4; s++) {
            const float* zin;
            if (s == 0) {
                zin = pZ;
            } else {
                float c1 = 0.f, c2 = 0.f, c3 = 0.f;
                if (s == 1)      { c1 = dt / 3.f; }
                else if (s == 2) { c1 = -dt / 3.f; c2 = dt; }
                else             { c1 = dt; c2 = -dt; c3 = dt; }
                zin_kernel<<<(BATCH * DIN + 255) / 256, 256>>>(c1, c2, c3);
                zin = pZIN;
            }
            // H = tanh(zin @ W1 + b1 + t*tw1)   [2048x1024, K=512]
            gemm_mma<128, 64, 1><<<dim3(HID / 64, BATCH / 128), 256, SM_BIG>>>(
                zin, pWB3, pH, BATCH, HID, DIN, b1, tw1, ts[s]);
            // K[s] = H @ W2 + b2                [2048x512, K=1024]
            gemm_mma<64, 64, 2><<<dim3(DIN / 64, BATCH / 64), 128, SM_G2>>>(
                pH, pW2T, pK + (size_t)s * BATCH * DIN, BATCH, DIN, HID, b2, nullptr, 0.f);

            // e keys: fk = tfry(k,(0,i)); k2 = tfry(fk,(0,1)); bits = xor-halves & 1
            uint32_t keys_e[2][2];
            for (int i = 0; i < 2; i++) {
                uint32_t f0, f1;
                tfry(sk[s][0], sk[s][1], 0u, (uint32_t)i, f0, f1);
                tfry(f0, f1, 0u, 1u, keys_e[i][0], keys_e[i][1]);
            }
            gen_e_kernel<<<dim3(BATCH * DIN / 256, 2), 256>>>(
                keys_e[0][0], keys_e[0][1], keys_e[1][0], keys_e[1][1]);

            // UV = [e1;e2] @ [W1 | W2^T]        [4096x2048, K=512]
            gemm_mma<128, 64, 0><<<dim3(2 * HID / 64, 2 * BATCH / 128), 256, SM_BIG>>>(
                pE, pWB3, pUV, 2 * BATCH, 2 * HID, DIN, nullptr, nullptr, 0.f);
            div_kernel<<<BATCH, 256>>>(s);
        }
        update_z<<<(BATCH * DIN + 255) / 256, 256>>>(dt * 0.125f);
        update_ll<<<(BATCH + 255) / 256, 256>>>(dt * 0.125f);
    }
    finalize_kernel<<<BATCH, 256>>>(out);
}

// round 7
// speedup vs baseline: 3.8982x; 1.2865x over previous
#include <cuda_runtime.h>
#include <cstdint>
#include <cstddef>

#define BATCH 2048
#define DIN   512
#define HID   1024
#define NSTEPS 9
#define CLAMPV 100.0f

// ---------------- scratch (static __device__, no allocations) ----------------
__device__ __align__(16) float g_Z[BATCH * DIN];
__device__ __align__(16) float g_LL[BATCH];
__device__ __align__(16) float g_ZIN[BATCH * DIN];
__device__ __align__(16) float g_K[4][BATCH * DIN];
__device__ __align__(16) float g_KD[4][BATCH];
__device__ __align__(16) float g_H[(size_t)BATCH * HID];
__device__ __align__(16) float g_E[(size_t)2 * BATCH * DIN];
__device__ __align__(16) float g_UV[(size_t)2 * BATCH * 2 * HID];
__device__ __align__(16) float g_WB3[(size_t)2 * HID * DIN];   // [W1^T ; W2] K-major, tf32-rounded
__device__ __align__(16) float g_W2T[(size_t)DIN * HID];       // W2^T K-major, tf32-rounded

// ---------------- threefry2x32 (exact JAX implementation) ----------------
__host__ __device__ inline uint32_t rotl32(uint32_t x, int d) {
    return (x << d) | (x >> (32 - d));
}
__host__ __device__ inline void tfry(uint32_t k0, uint32_t k1,
                                     uint32_t c0, uint32_t c1,
                                     uint32_t& o0, uint32_t& o1) {
    uint32_t ks0 = k0, ks1 = k1, ks2 = k0 ^ k1 ^ 0x1BD11BDAu;
    uint32_t x0 = c0 + ks0, x1 = c1 + ks1;
#define TF_ROUND(rot) { x0 += x1; x1 = rotl32(x1, rot) ^ x0; }
    TF_ROUND(13) TF_ROUND(15) TF_ROUND(26) TF_ROUND(6)
    x0 += ks1; x1 += ks2 + 1u;
    TF_ROUND(17) TF_ROUND(29) TF_ROUND(16) TF_ROUND(24)
    x0 += ks2; x1 += ks0 + 2u;
    TF_ROUND(13) TF_ROUND(15) TF_ROUND(26) TF_ROUND(6)
    x0 += ks0; x1 += ks1 + 3u;
    TF_ROUND(17) TF_ROUND(29) TF_ROUND(16) TF_ROUND(24)
    x0 += ks1; x1 += ks2 + 4u;
    TF_ROUND(13) TF_ROUND(15) TF_ROUND(26) TF_ROUND(6)
    x0 += ks2; x1 += ks0 + 5u;
#undef TF_ROUND
    o0 = x0; o1 = x1;
}

// ---------------- helpers ----------------
__device__ __forceinline__ float tf32r(float f) {
    uint32_t r; asm("cvt.rna.tf32.f32 %0, %1;" : "=r"(r) : "f"(f));
    return __uint_as_float(r);
}

#define MMA_TF32(d, a, b)                                                               \
    asm volatile(                                                                       \
        "mma.sync.aligned.m16n8k8.row.col.f32.tf32.tf32.f32 "                           \
        "{%0,%1,%2,%3}, {%4,%5,%6,%7}, {%8,%9}, {%0,%1,%2,%3};\n"                       \
        : "+f"((d)[0]), "+f"((d)[1]), "+f"((d)[2]), "+f"((d)[3])                        \
        : "r"((a)[0]), "r"((a)[1]), "r"((a)[2]), "r"((a)[3]), "r"((b)[0]), "r"((b)[1]))

#define LDMX4(r0, r1, r2, r3, addr)                                                     \
    asm volatile("ldmatrix.sync.aligned.m8n8.x4.shared.b16 {%0,%1,%2,%3}, [%4];"        \
                 : "=r"(r0), "=r"(r1), "=r"(r2), "=r"(r3) : "r"(addr))

#define CP16(dst, src) \
    asm volatile("cp.async.cg.shared.global [%0], [%1], 16;" :: "r"(dst), "l"(src) : "memory")
#define CP_COMMIT() asm volatile("cp.async.commit_group;" ::: "memory")
#define CP_WAIT1()  asm volatile("cp.async.wait_group 1;" ::: "memory")

__device__ inline float blockReduceSum(float v) {
    __shared__ float ws[8];
    int lane = threadIdx.x & 31, w = threadIdx.x >> 5;
#pragma unroll
    for (int o = 16; o > 0; o >>= 1) v += __shfl_down_sync(0xffffffffu, v, o);
    if (lane == 0) ws[w] = v;
    __syncthreads();
    if (w == 0) {
        v = (lane < ((int)blockDim.x >> 5)) ? ws[lane] : 0.f;
#pragma unroll
        for (int o = 4; o > 0; o >>= 1) v += __shfl_down_sync(0xffffffffu, v, o);
    }
    return v;
}

// ---------------- elementwise kernels ----------------
__global__ void init_kernel(const float* __restrict__ x) {
    int i = blockIdx.x * blockDim.x + threadIdx.x;
    if (i < BATCH * DIN) g_Z[i] = x[i];
    if (i < BATCH) g_LL[i] = 0.f;
}

// tf32-rounded weight builds (GEMM B operands)
__global__ void build_wb3(const float* __restrict__ W1, const float* __restrict__ W2) {
    int i = blockIdx.x * blockDim.x + threadIdx.x;
    if (i >= 2 * HID * DIN) return;
    int n = i / DIN, k = i % DIN;
    float v = (n < HID) ? W1[(size_t)k * HID + n] : W2[(size_t)(n - HID) * DIN + k];
    g_WB3[i] = tf32r(v);
}
__global__ void build_w2t(const float* __restrict__ W2) {
    int i = blockIdx.x * blockDim.x + threadIdx.x;
    if (i >= DIN * HID) return;
    int n = i / HID, k = i % HID;
    g_W2T[i] = tf32r(W2[(size_t)k * DIN + n]);
}

// ZIN = tf32_round(Z + c1 K0 + c2 K1 + c3 K2); useK=0 -> plain rounded copy of Z
__global__ void zin_kernel(float c1, float c2, float c3, int useK) {
    int i = blockIdx.x * blockDim.x + threadIdx.x;
    if (i >= BATCH * DIN) return;
    float v = g_Z[i];
    if (useK) v += c1 * g_K[0][i] + c2 * g_K[1][i] + c3 * g_K[2][i];
    g_ZIN[i] = tf32r(v);
}

__global__ void update_z(float dt8) {
    int i = blockIdx.x * blockDim.x + threadIdx.x;
    if (i >= BATCH * DIN) return;
    g_Z[i] += dt8 * (g_K[0][i] + 3.f * (g_K[1][i] + g_K[2][i]) + g_K[3][i]);
}

__global__ void update_ll(float dt8) {
    int b = blockIdx.x * blockDim.x + threadIdx.x;
    if (b >= BATCH) return;
    g_LL[b] += dt8 * (g_KD[0][b] + 3.f * (g_KD[1][b] + g_KD[2][b]) + g_KD[3][b]);
}

// JAX partitionable random_bits: bits[idx] = xor of outputs of threefry(key, (0, idx))
__global__ void gen_e_kernel(uint32_t k0a, uint32_t k1a, uint32_t k0b, uint32_t k1b) {
    int i = blockIdx.x * blockDim.x + threadIdx.x;
    if (i >= BATCH * DIN) return;
    uint32_t k0 = blockIdx.y ? k0b : k0a;
    uint32_t k1 = blockIdx.y ? k1b : k1a;
    uint32_t o0, o1;
    tfry(k0, k1, 0u, (uint32_t)i, o0, o1);
    g_E[(size_t)blockIdx.y * BATCH * DIN + i] = ((o0 ^ o1) & 1u) ? 1.f : -1.f;
}

__global__ void div_kernel(int s) {
    int b = blockIdx.x;
    const float* h   = g_H  + (size_t)b * HID;
    const float* uv1 = g_UV + (size_t)b * 2 * HID;
    const float* uv2 = g_UV + (size_t)(b + BATCH) * 2 * HID;
    float acc = 0.f;
    for (int k = threadIdx.x; k < HID; k += blockDim.x) {
        float hh = h[k];
        float g = 1.f - hh * hh;
        acc += g * (uv1[k] * uv1[HID + k] + uv2[k] * uv2[HID + k]);
    }
    float tot = blockReduceSum(acc);
    if (threadIdx.x == 0) {
        float d = 0.5f * tot;
        d = fminf(fmaxf(d, -CLAMPV), CLAMPV);
        g_KD[s][b] = -d;
    }
}

__global__ void finalize_kernel(float* __restrict__ out) {
    int b = blockIdx.x;
    float ssum = 0.f;
    for (int d = threadIdx.x; d < DIN; d += blockDim.x) {
        float v = g_Z[(size_t)b * DIN + d];
        out[(size_t)b * DIN + d] = v;
        ssum += v * v;
    }
    float tot = blockReduceSum(ssum);
    if (threadIdx.x == 0) out[(size_t)BATCH * DIN + b] = -0.5f * tot + g_LL[b];
}

// ---------------- tf32 mma.sync GEMM, cp.async 3-stage pipeline ----------------
// C[M,N] = A[M,K] @ Brows[N,K]^T.  Inputs already tf32-rounded in gmem.
// BK=32 floats.  3-stage cp.async smem pipeline, 16B XOR swizzle, ldmatrix frags.
// MODE 0: raw   MODE 1: tf32r(tanh(acc + bias + tval*tvec))   MODE 2: acc + bias
template <int BM, int BN, int MODE>
__global__ __launch_bounds__((BM / 32) * (BN / 32) * 32, 512 / ((BM / 32) * (BN / 32) * 32))
void gemm_mma(const float* __restrict__ A, const float* __restrict__ B,
              float* __restrict__ C, int M, int N, int K,
              const float* __restrict__ bias, const float* __restrict__ tvec, float tval) {
    extern __shared__ __align__(16) char smem[];
    constexpr int THREADS = (BM / 32) * (BN / 32) * 32;
    constexpr int WCOLS = BN / 32;
    constexpr int A16 = BM * 8 / THREADS;   // 16B chunks per thread, A tile (BM x 32 fl)
    constexpr int B16 = BN * 8 / THREADS;
    constexpr int ABYTES = BM * 128;
    constexpr int BBYTES = BN * 128;
    constexpr int STAGEB = ABYTES + BBYTES;

    float* sbias = (float*)smem;
    const uint32_t sA_u = (uint32_t)__cvta_generic_to_shared(smem + 1024);
    const uint32_t sB_u = sA_u + 3 * ABYTES;

    const int tid = threadIdx.x;
    const int lane = tid & 31;
    const int warp = tid >> 5;
    const int g = lane >> 2;
    const int tg = lane & 3;
    const int wrow = (warp / WCOLS) * 32;
    const int wcol = (warp % WCOLS) * 32;
    const int brow = blockIdx.y * BM;
    const int bcol = blockIdx.x * BN;

    if (MODE == 1 && tid < BN) sbias[tid] = bias[bcol + tid] + tval * tvec[bcol + tid];
    if (MODE == 2 && tid < BN) sbias[tid] = bias[bcol + tid];

    float acc[2][4][4];
#pragma unroll
    for (int i = 0; i < 2; i++)
#pragma unroll
        for (int j = 0; j < 4; j++)
#pragma unroll
            for (int q = 0; q < 4; q++) acc[i][j][q] = 0.f;

    // ldmatrix per-lane bases
    const int rA_l = wrow + (lane & 15);
    const int cA_l = lane >> 4;
    const int rB_l = wcol + ((lane >> 4) * 8) + (lane & 7);
    const int cB_l = (lane >> 3) & 1;

    const int nk = K >> 5;

#define ISSUE_COPY(st, kt)                                                              \
    do {                                                                                \
        _Pragma("unroll")                                                               \
        for (int i = 0; i < A16; i++) {                                                 \
            int f = tid + i * THREADS; int r = f >> 3, seg = f & 7;                     \
            uint32_t dst = sA_u + (st) * ABYTES + r * 128 + ((seg * 16) ^ ((r & 7) * 16)); \
            CP16(dst, A + (size_t)(brow + r) * K + (kt) + seg * 4);                     \
        }                                                                               \
        _Pragma("unroll")                                                               \
        for (int i = 0; i < B16; i++) {                                                 \
            int f = tid + i * THREADS; int r = f >> 3, seg = f & 7;                     \
            uint32_t dst = sB_u + (st) * BBYTES + r * 128 + ((seg * 16) ^ ((r & 7) * 16)); \
            CP16(dst, B + (size_t)(bcol + r) * K + (kt) + seg * 4);                     \
        }                                                                               \
    } while (0)

    // prologue: stages 0,1
    ISSUE_COPY(0, 0);
    CP_COMMIT();
    if (1 < nk) ISSUE_COPY(1, 32);
    CP_COMMIT();

    int t_issue = 2;
    for (int t = 0; t < nk; t++) {
        CP_WAIT1();
        __syncthreads();
        // issue next stage (into slot (t+2)%3 == (t-1+3)%3, readers done at iter t-1)
        if (t_issue < nk) {
            int st = t_issue - (t_issue / 3) * 3;
            ISSUE_COPY(st, t_issue << 5);
        }
        CP_COMMIT();
        t_issue++;

        const int slot = t - (t / 3) * 3;
        const uint32_t sa = sA_u + slot * ABYTES;
        const uint32_t sb = sB_u + slot * BBYTES;
#pragma unroll
        for (int ks = 0; ks < 4; ks++) {
            uint32_t af[2][4], bf[4][2];
#pragma unroll
            for (int mt = 0; mt < 2; mt++) {
                int r = rA_l + mt * 16;
                int ch = ks * 2 + cA_l;
                uint32_t addr = sa + r * 128 + ((ch * 16) ^ ((r & 7) * 16));
                LDMX4(af[mt][0], af[mt][1], af[mt][2], af[mt][3], addr);
            }
#pragma unroll
            for (int p = 0; p < 2; p++) {
                int r = rB_l + p * 16;
                int ch = ks * 2 + cB_l;
                uint32_t addr = sb + r * 128 + ((ch * 16) ^ ((r & 7) * 16));
                LDMX4(bf[2 * p][0], bf[2 * p][1], bf[2 * p + 1][0], bf[2 * p + 1][1], addr);
            }
#pragma unroll
            for (int mt = 0; mt < 2; mt++)
#pragma unroll
                for (int nt = 0; nt < 4; nt++)
                    MMA_TF32(acc[mt][nt], af[mt], bf[nt]);
        }
    }
#undef ISSUE_COPY

    // epilogue
#pragma unroll
    for (int mt = 0; mt < 2; mt++) {
#pragma unroll
        for (int nt = 0; nt < 4; nt++) {
            int lc = wcol + nt * 8 + tg * 2;
            int r0 = brow + wrow + mt * 16 + g;
            float v0 = acc[mt][nt][0], v1 = acc[mt][nt][1];
            float v2 = acc[mt][nt][2], v3 = acc[mt][nt][3];
            if (MODE == 1) {
                float b0 = sbias[lc], b1 = sbias[lc + 1];
                v0 = tf32r(tanhf(v0 + b0)); v1 = tf32r(tanhf(v1 + b1));
                v2 = tf32r(tanhf(v2 + b0)); v3 = tf32r(tanhf(v3 + b1));
            } else if (MODE == 2) {
                float b0 = sbias[lc], b1 = sbias[lc + 1];
                v0 += b0; v1 += b1; v2 += b0; v3 += b1;
            }
            *(float2*)(C + (size_t)r0 * N + bcol + lc)       = make_float2(v0, v1);
            *(float2*)(C + (size_t)(r0 + 8) * N + bcol + lc) = make_float2(v2, v3);
        }
    }
}

// ---------------- host orchestration ----------------
extern "C" void kernel_launch(void* const* d_in, const int* in_sizes, int n_in,
                              void* d_out, int out_size) {
    (void)in_sizes; (void)n_in; (void)out_size;
    const float* x   = (const float*)d_in[0];
    const float* W1  = (const float*)d_in[1];
    const float* b1  = (const float*)d_in[2];
    const float* tw1 = (const float*)d_in[3];
    const float* W2  = (const float*)d_in[4];
    const float* b2  = (const float*)d_in[5];
    float* out = (float*)d_out;

    float *pZIN, *pH, *pE, *pUV, *pWB3, *pW2T, *pK;
    cudaGetSymbolAddress((void**)&pZIN, g_ZIN);
    cudaGetSymbolAddress((void**)&pH, g_H);
    cudaGetSymbolAddress((void**)&pE, g_E);
    cudaGetSymbolAddress((void**)&pUV, g_UV);
    cudaGetSymbolAddress((void**)&pWB3, g_WB3);
    cudaGetSymbolAddress((void**)&pW2T, g_W2T);
    cudaGetSymbolAddress((void**)&pK, g_K);

    const int SM_BIG = 1024 + 3 * (128 + 64) * 128;  // 74752
    const int SM_G2  = 1024 + 3 * (64 + 64) * 128;   // 50176
    cudaFuncSetAttribute((const void*)gemm_mma<128, 64, 1>,
                         cudaFuncAttributeMaxDynamicSharedMemorySize, SM_BIG);
    cudaFuncSetAttribute((const void*)gemm_mma<64, 64, 2>,
                         cudaFuncAttributeMaxDynamicSharedMemorySize, SM_G2);
    cudaFuncSetAttribute((const void*)gemm_mma<128, 64, 0>,
                         cudaFuncAttributeMaxDynamicSharedMemorySize, SM_BIG);

    init_kernel<<<(BATCH * DIN + 255) / 256, 256>>>(x);
    build_wb3<<<(2 * HID * DIN + 255) / 256, 256>>>(W1, W2);
    build_w2t<<<(DIN * HID + 255) / 256, 256>>>(W2);

    // JAX threefry, partitionable semantics
    uint32_t key0 = 0u, key1 = 1234u;

    for (int step = 0; step < NSTEPS; step++) {
        uint32_t nk0, nk1;
        uint32_t sk[4][2];
        tfry(key0, key1, 0u, 0u, nk0, nk1);
        for (int s = 0; s < 4; s++)
            tfry(key0, key1, 0u, (uint32_t)(s + 1), sk[s][0], sk[s][1]);
        key0 = nk0; key1 = nk1;

        double t0d = (double)step / 9.0, t1d = (double)(step + 1) / 9.0;
        float t0 = (float)t0d;
        float dt = (float)(t1d - t0d);
        float ts[4] = {t0, t0 + dt / 3.f, t0 + 2.f * dt / 3.f, (float)t1d};

        for (int s = 0; s < 4; s++) {
            float c1 = 0.f, c2 = 0.f, c3 = 0.f;
            if (s == 1)      { c1 = dt / 3.f; }
            else if (s == 2) { c1 = -dt / 3.f; c2 = dt; }
            else if (s == 3) { c1 = dt; c2 = -dt; c3 = dt; }
            zin_kernel<<<(BATCH * DIN + 255) / 256, 256>>>(c1, c2, c3, s != 0);

            // H = tf32r(tanh(zin @ W1 + b1 + t*tw1))   [2048x1024, K=512]
            gemm_mma<128, 64, 1><<<dim3(HID / 64, BATCH / 128), 256, SM_BIG>>>(
                pZIN, pWB3, pH, BATCH, HID, DIN, b1, tw1, ts[s]);
            // K[s] = H @ W2 + b2                       [2048x512, K=1024]
            gemm_mma<64, 64, 2><<<dim3(DIN / 64, BATCH / 64), 128, SM_G2>>>(
                pH, pW2T, pK + (size_t)s * BATCH * DIN, BATCH, DIN, HID, b2, nullptr, 0.f);

            // e keys: fk = tfry(k,(0,i)); k2 = tfry(fk,(0,1)); bits = xor-halves & 1
            uint32_t keys_e[2][2];
            for (int i = 0; i < 2; i++) {
                uint32_t f0, f1;
                tfry(sk[s][0], sk[s][1], 0u, (uint32_t)i, f0, f1);
                tfry(f0, f1, 0u, 1u, keys_e[i][0], keys_e[i][1]);
            }
            gen_e_kernel<<<dim3(BATCH * DIN / 256, 2), 256>>>(
                keys_e[0][0], keys_e[0][1], keys_e[1][0], keys_e[1][1]);

            // UV = [e1;e2] @ [W1 | W2^T]               [4096x2048, K=512]
            gemm_mma<128, 64, 0><<<dim3(2 * HID / 64, 2 * BATCH / 128), 256, SM_BIG>>>(
                pE, pWB3, pUV, 2 * BATCH, 2 * HID, DIN, nullptr, nullptr, 0.f);
            div_kernel<<<BATCH, 256>>>(s);
        }
        update_z<<<(BATCH * DIN + 255) / 256, 256>>>(dt * 0.125f);
        update_ll<<<(BATCH + 255) / 256, 256>>>(dt * 0.125f);
    }
    finalize_kernel<<<BATCH, 256>>>(out);
}

// round 8
// speedup vs baseline: 4.1957x; 1.0763x over previous
#include <cuda_runtime.h>
#include <cstdint>
#include <cstddef>

#define BATCH 2048
#define DIN   512
#define HID   1024
#define NSTEPS 9
#define CLAMPV 100.0f

// ---------------- scratch (static __device__, no allocations) ----------------
__device__ __align__(16) float g_Z[BATCH * DIN];
__device__ __align__(16) float g_LL[BATCH];
__device__ __align__(16) float g_ZIN[BATCH * DIN];
__device__ __align__(16) float g_K[4][BATCH * DIN];
__device__ __align__(16) float g_KD[4][BATCH];          // raw div sums (atomic)
__device__ __align__(16) float g_H[(size_t)BATCH * HID];
__device__ __align__(16) float g_E[(size_t)2 * BATCH * DIN];
__device__ __align__(16) float g_W1T[(size_t)HID * DIN];      // W1^T K-major, tf32-rounded
__device__ __align__(16) float g_WIL[(size_t)2 * HID * DIN];  // interleaved [u_k;v_k] rows, tf32
__device__ __align__(16) float g_W2T[(size_t)DIN * HID];      // W2^T K-major, tf32-rounded

// ---------------- threefry2x32 (exact JAX implementation) ----------------
__host__ __device__ inline uint32_t rotl32(uint32_t x, int d) {
    return (x << d) | (x >> (32 - d));
}
__host__ __device__ inline void tfry(uint32_t k0, uint32_t k1,
                                     uint32_t c0, uint32_t c1,
                                     uint32_t& o0, uint32_t& o1) {
    uint32_t ks0 = k0, ks1 = k1, ks2 = k0 ^ k1 ^ 0x1BD11BDAu;
    uint32_t x0 = c0 + ks0, x1 = c1 + ks1;
#define TF_ROUND(rot) { x0 += x1; x1 = rotl32(x1, rot) ^ x0; }
    TF_ROUND(13) TF_ROUND(15) TF_ROUND(26) TF_ROUND(6)
    x0 += ks1; x1 += ks2 + 1u;
    TF_ROUND(17) TF_ROUND(29) TF_ROUND(16) TF_ROUND(24)
    x0 += ks2; x1 += ks0 + 2u;
    TF_ROUND(13) TF_ROUND(15) TF_ROUND(26) TF_ROUND(6)
    x0 += ks0; x1 += ks1 + 3u;
    TF_ROUND(17) TF_ROUND(29) TF_ROUND(16) TF_ROUND(24)
    x0 += ks1; x1 += ks2 + 4u;
    TF_ROUND(13) TF_ROUND(15) TF_ROUND(26) TF_ROUND(6)
    x0 += ks2; x1 += ks0 + 5u;
#undef TF_ROUND
    o0 = x0; o1 = x1;
}

// ---------------- helpers ----------------
__device__ __forceinline__ float tf32r(float f) {
    uint32_t r; asm("cvt.rna.tf32.f32 %0, %1;" : "=r"(r) : "f"(f));
    return __uint_as_float(r);
}

#define MMA_TF32(d, a, b)                                                               \
    asm volatile(                                                                       \
        "mma.sync.aligned.m16n8k8.row.col.f32.tf32.tf32.f32 "                           \
        "{%0,%1,%2,%3}, {%4,%5,%6,%7}, {%8,%9}, {%0,%1,%2,%3};\n"                       \
        : "+f"((d)[0]), "+f"((d)[1]), "+f"((d)[2]), "+f"((d)[3])                        \
        : "r"((a)[0]), "r"((a)[1]), "r"((a)[2]), "r"((a)[3]), "r"((b)[0]), "r"((b)[1]))

#define LDMX4(r0, r1, r2, r3, addr)                                                     \
    asm volatile("ldmatrix.sync.aligned.m8n8.x4.shared.b16 {%0,%1,%2,%3}, [%4];"        \
                 : "=r"(r0), "=r"(r1), "=r"(r2), "=r"(r3) : "r"(addr))

#define CP16(dst, src) \
    asm volatile("cp.async.cg.shared.global [%0], [%1], 16;" :: "r"(dst), "l"(src) : "memory")
#define CP_COMMIT() asm volatile("cp.async.commit_group;" ::: "memory")
#define CP_WAIT1()  asm volatile("cp.async.wait_group 1;" ::: "memory")

__device__ inline float blockReduceSum(float v) {
    __shared__ float ws[8];
    int lane = threadIdx.x & 31, w = threadIdx.x >> 5;
#pragma unroll
    for (int o = 16; o > 0; o >>= 1) v += __shfl_down_sync(0xffffffffu, v, o);
    if (lane == 0) ws[w] = v;
    __syncthreads();
    if (w == 0) {
        v = (lane < ((int)blockDim.x >> 5)) ? ws[lane] : 0.f;
#pragma unroll
        for (int o = 4; o > 0; o >>= 1) v += __shfl_down_sync(0xffffffffu, v, o);
    }
    return v;
}

// ---------------- elementwise kernels ----------------
__global__ void init_kernel(const float* __restrict__ x) {
    int i = blockIdx.x * blockDim.x + threadIdx.x;
    if (i < BATCH * DIN) { float v = x[i]; g_Z[i] = v; g_ZIN[i] = tf32r(v); }
    if (i < BATCH) g_LL[i] = 0.f;
}

// weight builds (tf32-rounded GEMM B operands)
__global__ void build_w1t(const float* __restrict__ W1) {
    int i = blockIdx.x * blockDim.x + threadIdx.x;
    if (i >= HID * DIN) return;
    int n = i / DIN, k = i % DIN;
    g_W1T[i] = tf32r(W1[(size_t)k * HID + n]);
}
// interleaved: row 2k = W1[:,k] (u), row 2k+1 = W2[k,:] (v)
__global__ void build_wil(const float* __restrict__ W1, const float* __restrict__ W2) {
    int i = blockIdx.x * blockDim.x + threadIdx.x;
    if (i >= 2 * HID * DIN) return;
    int n = i / DIN, d = i % DIN;
    int k = n >> 1;
    float v = (n & 1) ? W2[(size_t)k * DIN + d] : W1[(size_t)d * HID + k];
    g_WIL[i] = tf32r(v);
}
__global__ void build_w2t(const float* __restrict__ W2) {
    int i = blockIdx.x * blockDim.x + threadIdx.x;
    if (i >= DIN * HID) return;
    int n = i / HID, k = i % HID;
    g_W2T[i] = tf32r(W2[(size_t)k * DIN + n]);
}

// ZIN = tf32_round(Z + c1 K0 + c2 K1 + c3 K2)   (stages 1..3 only)
__global__ void zin_kernel(float c1, float c2, float c3) {
    int i = blockIdx.x * blockDim.x + threadIdx.x;
    if (i >= BATCH * DIN) return;
    float v = g_Z[i] + c1 * g_K[0][i] + c2 * g_K[1][i] + c3 * g_K[2][i];
    g_ZIN[i] = tf32r(v);
}

// Z update + ZIN refresh + LL update (merged)
__global__ void update_step(float dt8) {
    int i = blockIdx.x * blockDim.x + threadIdx.x;
    if (i < BATCH * DIN) {
        float z = g_Z[i] + dt8 * (g_K[0][i] + 3.f * (g_K[1][i] + g_K[2][i]) + g_K[3][i]);
        g_Z[i] = z;
        g_ZIN[i] = tf32r(z);
    }
    if (i < BATCH) {
        float d[4];
#pragma unroll
        for (int s = 0; s < 4; s++) {
            float v = 0.5f * g_KD[s][i];
            d[s] = fminf(fmaxf(v, -CLAMPV), CLAMPV);
        }
        g_LL[i] += dt8 * (-d[0] - 3.f * (d[1] + d[2]) - d[3]);
    }
}

// e gen + zero this stage's KD accumulator
__global__ void gen_e_kernel(uint32_t k0a, uint32_t k1a, uint32_t k0b, uint32_t k1b,
                             float* __restrict__ kdraw) {
    int i = blockIdx.x * blockDim.x + threadIdx.x;
    if (i >= BATCH * DIN) return;
    uint32_t k0 = blockIdx.y ? k0b : k0a;
    uint32_t k1 = blockIdx.y ? k1b : k1a;
    uint32_t o0, o1;
    tfry(k0, k1, 0u, (uint32_t)i, o0, o1);
    g_E[(size_t)blockIdx.y * BATCH * DIN + i] = ((o0 ^ o1) & 1u) ? 1.f : -1.f;
    if (blockIdx.y == 0 && i < BATCH) kdraw[i] = 0.f;
}

__global__ void finalize_kernel(float* __restrict__ out) {
    int b = blockIdx.x;
    float ssum = 0.f;
    for (int d = threadIdx.x; d < DIN; d += blockDim.x) {
        float v = g_Z[(size_t)b * DIN + d];
        out[(size_t)b * DIN + d] = v;
        ssum += v * v;
    }
    float tot = blockReduceSum(ssum);
    if (threadIdx.x == 0) out[(size_t)BATCH * DIN + b] = -0.5f * tot + g_LL[b];
}

// ---------------- tf32 mma.sync GEMM, cp.async 3-stage pipeline ----------------
// C[M,N] = A[M,K] @ Brows[N,K]^T.  Inputs already tf32-rounded in gmem.
// MODE 0: raw store  MODE 1: tf32r(tanh(acc+bias+tval*tvec))  MODE 2: acc+bias
// MODE 3: no store; B cols are (u,v) pairs; accumulate sum_k (1-h^2) u v into kdraw[b]
template <int BM, int BN, int MODE>
__global__ __launch_bounds__((BM / 32) * (BN / 32) * 32, 512 / ((BM / 32) * (BN / 32) * 32))
void gemm_mma(const float* __restrict__ A, const float* __restrict__ B,
              float* __restrict__ C, int M, int N, int K,
              const float* __restrict__ bias, const float* __restrict__ tvec, float tval) {
    extern __shared__ __align__(16) char smem[];
    constexpr int THREADS = (BM / 32) * (BN / 32) * 32;
    constexpr int WCOLS = BN / 32;
    constexpr int A16 = BM * 8 / THREADS;
    constexpr int B16 = BN * 8 / THREADS;
    constexpr int ABYTES = BM * 128;
    constexpr int BBYTES = BN * 128;

    float* sbias = (float*)smem;
    const uint32_t sA_u = (uint32_t)__cvta_generic_to_shared(smem + 1024);
    const uint32_t sB_u = sA_u + 3 * ABYTES;

    const int tid = threadIdx.x;
    const int lane = tid & 31;
    const int warp = tid >> 5;
    const int g = lane >> 2;
    const int tg = lane & 3;
    const int wrow = (warp / WCOLS) * 32;
    const int wcol = (warp % WCOLS) * 32;
    const int brow = blockIdx.y * BM;
    const int bcol = blockIdx.x * BN;

    if (MODE == 1 && tid < BN) sbias[tid] = bias[bcol + tid] + tval * tvec[bcol + tid];
    if (MODE == 2 && tid < BN) sbias[tid] = bias[bcol + tid];

    float acc[2][4][4];
#pragma unroll
    for (int i = 0; i < 2; i++)
#pragma unroll
        for (int j = 0; j < 4; j++)
#pragma unroll
            for (int q = 0; q < 4; q++) acc[i][j][q] = 0.f;

    const int rA_l = wrow + (lane & 15);
    const int cA_l = lane >> 4;
    const int rB_l = wcol + ((lane >> 4) * 8) + (lane & 7);
    const int cB_l = (lane >> 3) & 1;

    const int nk = K >> 5;

#define ISSUE_COPY(st, kt)                                                              \
    do {                                                                                \
        _Pragma("unroll")                                                               \
        for (int i = 0; i < A16; i++) {                                                 \
            int f = tid + i * THREADS; int r = f >> 3, seg = f & 7;                     \
            uint32_t dst = sA_u + (st) * ABYTES + r * 128 + ((seg * 16) ^ ((r & 7) * 16)); \
            CP16(dst, A + (size_t)(brow + r) * K + (kt) + seg * 4);                     \
        }                                                                               \
        _Pragma("unroll")                                                               \
        for (int i = 0; i < B16; i++) {                                                 \
            int f = tid + i * THREADS; int r = f >> 3, seg = f & 7;                     \
            uint32_t dst = sB_u + (st) * BBYTES + r * 128 + ((seg * 16) ^ ((r & 7) * 16)); \
            CP16(dst, B + (size_t)(bcol + r) * K + (kt) + seg * 4);                     \
        }                                                                               \
    } while (0)

    ISSUE_COPY(0, 0);
    CP_COMMIT();
    if (1 < nk) ISSUE_COPY(1, 32);
    CP_COMMIT();

    int t_issue = 2;
    for (int t = 0; t < nk; t++) {
        CP_WAIT1();
        __syncthreads();
        if (t_issue < nk) {
            int st = t_issue - (t_issue / 3) * 3;
            ISSUE_COPY(st, t_issue << 5);
        }
        CP_COMMIT();
        t_issue++;

        const int slot = t - (t / 3) * 3;
        const uint32_t sa = sA_u + slot * ABYTES;
        const uint32_t sb = sB_u + slot * BBYTES;
#pragma unroll
        for (int ks = 0; ks < 4; ks++) {
            uint32_t af[2][4], bf[4][2];
#pragma unroll
            for (int mt = 0; mt < 2; mt++) {
                int r = rA_l + mt * 16;
                int ch = ks * 2 + cA_l;
                uint32_t addr = sa + r * 128 + ((ch * 16) ^ ((r & 7) * 16));
                LDMX4(af[mt][0], af[mt][1], af[mt][2], af[mt][3], addr);
            }
#pragma unroll
            for (int p = 0; p < 2; p++) {
                int r = rB_l + p * 16;
                int ch = ks * 2 + cB_l;
                uint32_t addr = sb + r * 128 + ((ch * 16) ^ ((r & 7) * 16));
                LDMX4(bf[2 * p][0], bf[2 * p][1], bf[2 * p + 1][0], bf[2 * p + 1][1], addr);
            }
#pragma unroll
            for (int mt = 0; mt < 2; mt++)
#pragma unroll
                for (int nt = 0; nt < 4; nt++)
                    MMA_TF32(acc[mt][nt], af[mt], bf[nt]);
        }
    }
#undef ISSUE_COPY

    if (MODE == 3) {
        // bias = h matrix [BATCH, HID]; tvec = kdraw accumulator [BATCH]
        const float* hmat = bias;
        float* kdraw = (float*)tvec;
        const int kbase = ((bcol + wcol) >> 1) + tg;  // pair index, +nt*4
#pragma unroll
        for (int mt = 0; mt < 2; mt++) {
            int r0 = brow + wrow + mt * 16 + g;
            int b0 = r0 & (BATCH - 1);
            int b1 = (r0 + 8) & (BATCH - 1);
            float s0 = 0.f, s1 = 0.f;
#pragma unroll
            for (int nt = 0; nt < 4; nt++) {
                int kk = kbase + nt * 4;
                float h0 = hmat[(size_t)b0 * HID + kk];
                float h1 = hmat[(size_t)b1 * HID + kk];
                s0 += (1.f - h0 * h0) * acc[mt][nt][0] * acc[mt][nt][1];
                s1 += (1.f - h1 * h1) * acc[mt][nt][2] * acc[mt][nt][3];
            }
            s0 += __shfl_xor_sync(0xffffffffu, s0, 1);
            s0 += __shfl_xor_sync(0xffffffffu, s0, 2);
            s1 += __shfl_xor_sync(0xffffffffu, s1, 1);
            s1 += __shfl_xor_sync(0xffffffffu, s1, 2);
            if (tg == 0) {
                atomicAdd(&kdraw[b0], s0);
                atomicAdd(&kdraw[b1], s1);
            }
        }
        return;
    }

    // epilogue (store modes)
#pragma unroll
    for (int mt = 0; mt < 2; mt++) {
#pragma unroll
        for (int nt = 0; nt < 4; nt++) {
            int lc = wcol + nt * 8 + tg * 2;
            int r0 = brow + wrow + mt * 16 + g;
            float v0 = acc[mt][nt][0], v1 = acc[mt][nt][1];
            float v2 = acc[mt][nt][2], v3 = acc[mt][nt][3];
            if (MODE == 1) {
                float b0 = sbias[lc], b1 = sbias[lc + 1];
                v0 = tf32r(tanhf(v0 + b0)); v1 = tf32r(tanhf(v1 + b1));
                v2 = tf32r(tanhf(v2 + b0)); v3 = tf32r(tanhf(v3 + b1));
            } else if (MODE == 2) {
                float b0 = sbias[lc], b1 = sbias[lc + 1];
                v0 += b0; v1 += b1; v2 += b0; v3 += b1;
            }
            *(float2*)(C + (size_t)r0 * N + bcol + lc)       = make_float2(v0, v1);
            *(float2*)(C + (size_t)(r0 + 8) * N + bcol + lc) = make_float2(v2, v3);
        }
    }
}

// ---------------- host orchestration ----------------
extern "C" void kernel_launch(void* const* d_in, const int* in_sizes, int n_in,
                              void* d_out, int out_size) {
    (void)in_sizes; (void)n_in; (void)out_size;
    const float* x   = (const float*)d_in[0];
    const float* W1  = (const float*)d_in[1];
    const float* b1  = (const float*)d_in[2];
    const float* tw1 = (const float*)d_in[3];
    const float* W2  = (const float*)d_in[4];
    const float* b2  = (const float*)d_in[5];
    float* out = (float*)d_out;

    float *pZIN, *pH, *pE, *pW1T, *pWIL, *pW2T, *pK, *pKD;
    cudaGetSymbolAddress((void**)&pZIN, g_ZIN);
    cudaGetSymbolAddress((void**)&pH, g_H);
    cudaGetSymbolAddress((void**)&pE, g_E);
    cudaGetSymbolAddress((void**)&pW1T, g_W1T);
    cudaGetSymbolAddress((void**)&pWIL, g_WIL);
    cudaGetSymbolAddress((void**)&pW2T, g_W2T);
    cudaGetSymbolAddress((void**)&pK, g_K);
    cudaGetSymbolAddress((void**)&pKD, g_KD);

    const int SM_BIG = 1024 + 3 * (128 + 64) * 128;  // 74752
    const int SM_G2  = 1024 + 3 * (64 + 64) * 128;   // 50176
    cudaFuncSetAttribute((const void*)gemm_mma<128, 64, 1>,
                         cudaFuncAttributeMaxDynamicSharedMemorySize, SM_BIG);
    cudaFuncSetAttribute((const void*)gemm_mma<64, 64, 2>,
                         cudaFuncAttributeMaxDynamicSharedMemorySize, SM_G2);
    cudaFuncSetAttribute((const void*)gemm_mma<128, 64, 3>,
                         cudaFuncAttributeMaxDynamicSharedMemorySize, SM_BIG);

    init_kernel<<<(BATCH * DIN + 255) / 256, 256>>>(x);
    build_w1t<<<(HID * DIN + 255) / 256, 256>>>(W1);
    build_wil<<<(2 * HID * DIN + 255) / 256, 256>>>(W1, W2);
    build_w2t<<<(DIN * HID + 255) / 256, 256>>>(W2);

    // JAX threefry, partitionable semantics
    uint32_t key0 = 0u, key1 = 1234u;

    for (int step = 0; step < NSTEPS; step++) {
        uint32_t nk0, nk1;
        uint32_t sk[4][2];
        tfry(key0, key1, 0u, 0u, nk0, nk1);
        for (int s = 0; s < 4; s++)
            tfry(key0, key1, 0u, (uint32_t)(s + 1), sk[s][0], sk[s][1]);
        key0 = nk0; key1 = nk1;

        double t0d = (double)step / 9.0, t1d = (double)(step + 1) / 9.0;
        float t0 = (float)t0d;
        float dt = (float)(t1d - t0d);
        float ts[4] = {t0, t0 + dt / 3.f, t0 + 2.f * dt / 3.f, (float)t1d};

        for (int s = 0; s < 4; s++) {
            if (s == 1)      zin_kernel<<<(BATCH * DIN + 255) / 256, 256>>>(dt / 3.f, 0.f, 0.f);
            else if (s == 2) zin_kernel<<<(BATCH * DIN + 255) / 256, 256>>>(-dt / 3.f, dt, 0.f);
            else if (s == 3) zin_kernel<<<(BATCH * DIN + 255) / 256, 256>>>(dt, -dt, dt);
            // (s == 0: ZIN already holds tf32r(Z))

            // H = tf32r(tanh(zin @ W1 + b1 + t*tw1))   [2048x1024, K=512]
            gemm_mma<128, 64, 1><<<dim3(HID / 64, BATCH / 128), 256, SM_BIG>>>(
                pZIN, pW1T, pH, BATCH, HID, DIN, b1, tw1, ts[s]);
            // K[s] = H @ W2 + b2                       [2048x512, K=1024]
            gemm_mma<64, 64, 2><<<dim3(DIN / 64, BATCH / 64), 128, SM_G2>>>(
                pH, pW2T, pK + (size_t)s * BATCH * DIN, BATCH, DIN, HID, b2, nullptr, 0.f);

            // e keys: fk = tfry(k,(0,i)); k2 = tfry(fk,(0,1)); bits = xor-halves & 1
            uint32_t keys_e[2][2];
            for (int i = 0; i < 2; i++) {
                uint32_t f0, f1;
                tfry(sk[s][0], sk[s][1], 0u, (uint32_t)i, f0, f1);
                tfry(f0, f1, 0u, 1u, keys_e[i][0], keys_e[i][1]);
            }
            gen_e_kernel<<<dim3(BATCH * DIN / 256, 2), 256>>>(
                keys_e[0][0], keys_e[0][1], keys_e[1][0], keys_e[1][1],
                pKD + (size_t)s * BATCH);

            // fused trace GEMM + divergence reduction    [4096x2048, K=512]
            gemm_mma<128, 64, 3><<<dim3(2 * HID / 64, 2 * BATCH / 128), 256, SM_BIG>>>(
                pE, pWIL, nullptr, 2 * BATCH, 2 * HID, DIN,
                pH, pKD + (size_t)s * BATCH, 0.f);
        }
        update_step<<<(BATCH * DIN + 255) / 256, 256>>>(dt * 0.125f);
    }
    finalize_kernel<<<BATCH, 256>>>(out);
}

// round 9
// speedup vs baseline: 6.7115x; 1.5996x over previous
#include <cuda_runtime.h>
#include <cuda_fp16.h>
#include <cstdint>
#include <cstddef>

#define BATCH 2048
#define DIN   512
#define HID   1024
#define NSTEPS 9
#define CLAMPV 100.0f

// ---------------- scratch (static __device__, no allocations) ----------------
__device__ __align__(16) float  g_Z[BATCH * DIN];
__device__ __align__(16) float  g_LL[BATCH];
__device__ __align__(16) __half g_ZIN[BATCH * DIN];
__device__ __align__(16) float  g_K[4][BATCH * DIN];
__device__ __align__(16) float  g_KD[4][BATCH];           // raw div sums (atomic)
__device__ __align__(16) __half g_H[(size_t)BATCH * HID];
__device__ __align__(16) __half g_E[(size_t)2 * BATCH * DIN];
__device__ __align__(16) __half g_W1T[(size_t)HID * DIN];      // W1^T K-major
__device__ __align__(16) __half g_WIL[(size_t)2 * HID * DIN];  // interleaved [u_k;v_k] rows
__device__ __align__(16) __half g_W2T[(size_t)DIN * HID];      // W2^T K-major

// ---------------- threefry2x32 (exact JAX implementation) ----------------
__host__ __device__ inline uint32_t rotl32(uint32_t x, int d) {
    return (x << d) | (x >> (32 - d));
}
__host__ __device__ inline void tfry(uint32_t k0, uint32_t k1,
                                     uint32_t c0, uint32_t c1,
                                     uint32_t& o0, uint32_t& o1) {
    uint32_t ks0 = k0, ks1 = k1, ks2 = k0 ^ k1 ^ 0x1BD11BDAu;
    uint32_t x0 = c0 + ks0, x1 = c1 + ks1;
#define TF_ROUND(rot) { x0 += x1; x1 = rotl32(x1, rot) ^ x0; }
    TF_ROUND(13) TF_ROUND(15) TF_ROUND(26) TF_ROUND(6)
    x0 += ks1; x1 += ks2 + 1u;
    TF_ROUND(17) TF_ROUND(29) TF_ROUND(16) TF_ROUND(24)
    x0 += ks2; x1 += ks0 + 2u;
    TF_ROUND(13) TF_ROUND(15) TF_ROUND(26) TF_ROUND(6)
    x0 += ks0; x1 += ks1 + 3u;
    TF_ROUND(17) TF_ROUND(29) TF_ROUND(16) TF_ROUND(24)
    x0 += ks1; x1 += ks2 + 4u;
    TF_ROUND(13) TF_ROUND(15) TF_ROUND(26) TF_ROUND(6)
    x0 += ks2; x1 += ks0 + 5u;
#undef TF_ROUND
    o0 = x0; o1 = x1;
}

// ---------------- helpers ----------------
#define MMA_F16(d, a, b)                                                                \
    asm volatile(                                                                       \
        "mma.sync.aligned.m16n8k16.row.col.f32.f16.f16.f32 "                            \
        "{%0,%1,%2,%3}, {%4,%5,%6,%7}, {%8,%9}, {%0,%1,%2,%3};\n"                       \
        : "+f"((d)[0]), "+f"((d)[1]), "+f"((d)[2]), "+f"((d)[3])                        \
        : "r"((a)[0]), "r"((a)[1]), "r"((a)[2]), "r"((a)[3]), "r"((b)[0]), "r"((b)[1]))

#define LDMX4(r0, r1, r2, r3, addr)                                                     \
    asm volatile("ldmatrix.sync.aligned.m8n8.x4.shared.b16 {%0,%1,%2,%3}, [%4];"        \
                 : "=r"(r0), "=r"(r1), "=r"(r2), "=r"(r3) : "r"(addr))

#define CP16(dst, src) \
    asm volatile("cp.async.cg.shared.global [%0], [%1], 16;" :: "r"(dst), "l"(src) : "memory")
#define CP_COMMIT() asm volatile("cp.async.commit_group;" ::: "memory")
#define CP_WAIT1()  asm volatile("cp.async.wait_group 1;" ::: "memory")

__device__ inline float blockReduceSum(float v) {
    __shared__ float ws[8];
    int lane = threadIdx.x & 31, w = threadIdx.x >> 5;
#pragma unroll
    for (int o = 16; o > 0; o >>= 1) v += __shfl_down_sync(0xffffffffu, v, o);
    if (lane == 0) ws[w] = v;
    __syncthreads();
    if (w == 0) {
        v = (lane < ((int)blockDim.x >> 5)) ? ws[lane] : 0.f;
#pragma unroll
        for (int o = 4; o > 0; o >>= 1) v += __shfl_down_sync(0xffffffffu, v, o);
    }
    return v;
}

// ---------------- elementwise kernels ----------------
__global__ void init_kernel(const float* __restrict__ x) {
    int i = blockIdx.x * blockDim.x + threadIdx.x;
    if (i < BATCH * DIN) { float v = x[i]; g_Z[i] = v; g_ZIN[i] = __float2half_rn(v); }
    if (i < BATCH) g_LL[i] = 0.f;
}

// weight builds (fp16 GEMM B operands)
__global__ void build_w1t(const float* __restrict__ W1) {
    int i = blockIdx.x * blockDim.x + threadIdx.x;
    if (i >= HID * DIN) return;
    int n = i / DIN, k = i % DIN;
    g_W1T[i] = __float2half_rn(W1[(size_t)k * HID + n]);
}
// interleaved: row 2k = W1[:,k] (u), row 2k+1 = W2[k,:] (v)
__global__ void build_wil(const float* __restrict__ W1, const float* __restrict__ W2) {
    int i = blockIdx.x * blockDim.x + threadIdx.x;
    if (i >= 2 * HID * DIN) return;
    int n = i / DIN, d = i % DIN;
    int k = n >> 1;
    float v = (n & 1) ? W2[(size_t)k * DIN + d] : W1[(size_t)d * HID + k];
    g_WIL[i] = __float2half_rn(v);
}
__global__ void build_w2t(const float* __restrict__ W2) {
    int i = blockIdx.x * blockDim.x + threadIdx.x;
    if (i >= DIN * HID) return;
    int n = i / HID, k = i % HID;
    g_W2T[i] = __float2half_rn(W2[(size_t)k * DIN + n]);
}

// ZIN = fp16_round(Z + c1 K0 + c2 K1 + c3 K2)   (stages 1..3 only)
__global__ void zin_kernel(float c1, float c2, float c3) {
    int i = blockIdx.x * blockDim.x + threadIdx.x;
    if (i >= BATCH * DIN) return;
    float v = g_Z[i] + c1 * g_K[0][i] + c2 * g_K[1][i] + c3 * g_K[2][i];
    g_ZIN[i] = __float2half_rn(v);
}

// Z update + ZIN refresh + LL update (merged)
__global__ void update_step(float dt8) {
    int i = blockIdx.x * blockDim.x + threadIdx.x;
    if (i < BATCH * DIN) {
        float z = g_Z[i] + dt8 * (g_K[0][i] + 3.f * (g_K[1][i] + g_K[2][i]) + g_K[3][i]);
        g_Z[i] = z;
        g_ZIN[i] = __float2half_rn(z);
    }
    if (i < BATCH) {
        float d[4];
#pragma unroll
        for (int s = 0; s < 4; s++) {
            float v = 0.5f * g_KD[s][i];
            d[s] = fminf(fmaxf(v, -CLAMPV), CLAMPV);
        }
        g_LL[i] += dt8 * (-d[0] - 3.f * (d[1] + d[2]) - d[3]);
    }
}

// e gen + zero this stage's KD accumulator
__global__ void gen_e_kernel(uint32_t k0a, uint32_t k1a, uint32_t k0b, uint32_t k1b,
                             float* __restrict__ kdraw) {
    int i = blockIdx.x * blockDim.x + threadIdx.x;
    if (i >= BATCH * DIN) return;
    uint32_t k0 = blockIdx.y ? k0b : k0a;
    uint32_t k1 = blockIdx.y ? k1b : k1a;
    uint32_t o0, o1;
    tfry(k0, k1, 0u, (uint32_t)i, o0, o1);
    g_E[(size_t)blockIdx.y * BATCH * DIN + i] =
        ((o0 ^ o1) & 1u) ? __float2half_rn(1.f) : __float2half_rn(-1.f);
    if (blockIdx.y == 0 && i < BATCH) kdraw[i] = 0.f;
}

__global__ void finalize_kernel(float* __restrict__ out) {
    int b = blockIdx.x;
    float ssum = 0.f;
    for (int d = threadIdx.x; d < DIN; d += blockDim.x) {
        float v = g_Z[(size_t)b * DIN + d];
        out[(size_t)b * DIN + d] = v;
        ssum += v * v;
    }
    float tot = blockReduceSum(ssum);
    if (threadIdx.x == 0) out[(size_t)BATCH * DIN + b] = -0.5f * tot + g_LL[b];
}

// ---------------- fp16 mma.sync GEMM, cp.async 3-stage pipeline ----------------
// C[M,N] = A[M,K] @ Brows[N,K]^T, fp16 operands, fp32 accumulate.
// k-tile = 64 halves = 128B/row, 16B-chunk XOR swizzle, ldmatrix fragments.
// MODE 1: H[half] = fp16(tanh(acc+bias+tval*tvec))   MODE 2: C[float] = acc+bias
// MODE 3: no store; B cols (u,v)-interleaved; kdraw[b] += sum_k (1-h^2) u v
template <int BM, int BN, int MODE>
__global__ __launch_bounds__((BM / 32) * (BN / 32) * 32, 512 / ((BM / 32) * (BN / 32) * 32))
void gemm_mma(const __half* __restrict__ A, const __half* __restrict__ B,
              void* __restrict__ Cv, int M, int N, int K,
              const void* __restrict__ biasv, void* __restrict__ auxv, float tval) {
    extern __shared__ __align__(16) char smem[];
    constexpr int THREADS = (BM / 32) * (BN / 32) * 32;
    constexpr int WCOLS = BN / 32;
    constexpr int A16 = BM * 8 / THREADS;   // 16B chunks per thread (tile = BM x 8 chunks)
    constexpr int B16 = BN * 8 / THREADS;
    constexpr int ABYTES = BM * 128;
    constexpr int BBYTES = BN * 128;

    float* sbias = (float*)smem;
    const uint32_t sA_u = (uint32_t)__cvta_generic_to_shared(smem + 1024);
    const uint32_t sB_u = sA_u + 3 * ABYTES;

    const int tid = threadIdx.x;
    const int lane = tid & 31;
    const int warp = tid >> 5;
    const int g = lane >> 2;
    const int tg = lane & 3;
    const int wrow = (warp / WCOLS) * 32;
    const int wcol = (warp % WCOLS) * 32;
    const int brow = blockIdx.y * BM;
    const int bcol = blockIdx.x * BN;

    if (MODE == 1 && tid < BN) {
        const float* bias = (const float*)biasv;
        const float* tvec = (const float*)auxv;
        sbias[tid] = bias[bcol + tid] + tval * tvec[bcol + tid];
    }
    if (MODE == 2 && tid < BN) sbias[tid] = ((const float*)biasv)[bcol + tid];

    float acc[2][4][4];
#pragma unroll
    for (int i = 0; i < 2; i++)
#pragma unroll
        for (int j = 0; j < 4; j++)
#pragma unroll
            for (int q = 0; q < 4; q++) acc[i][j][q] = 0.f;

    const int rA_l = wrow + (lane & 15);
    const int cA_l = lane >> 4;
    const int rB_l = wcol + ((lane >> 4) * 8) + (lane & 7);
    const int cB_l = (lane >> 3) & 1;

    const int nk = K >> 6;   // 64 halves per k-tile

#define ISSUE_COPY(st, kt)                                                              \
    do {                                                                                \
        _Pragma("unroll")                                                               \
        for (int i = 0; i < A16; i++) {                                                 \
            int f = tid + i * THREADS; int r = f >> 3, seg = f & 7;                     \
            uint32_t dst = sA_u + (st) * ABYTES + r * 128 + ((seg * 16) ^ ((r & 7) * 16)); \
            CP16(dst, A + (size_t)(brow + r) * K + (kt) + seg * 8);                     \
        }                                                                               \
        _Pragma("unroll")                                                               \
        for (int i = 0; i < B16; i++) {                                                 \
            int f = tid + i * THREADS; int r = f >> 3, seg = f & 7;                     \
            uint32_t dst = sB_u + (st) * BBYTES + r * 128 + ((seg * 16) ^ ((r & 7) * 16)); \
            CP16(dst, B + (size_t)(bcol + r) * K + (kt) + seg * 8);                     \
        }                                                                               \
    } while (0)

    ISSUE_COPY(0, 0);
    CP_COMMIT();
    if (1 < nk) ISSUE_COPY(1, 64);
    CP_COMMIT();

    int t_issue = 2;
    for (int t = 0; t < nk; t++) {
        CP_WAIT1();
        __syncthreads();
        if (t_issue < nk) {
            int st = t_issue - (t_issue / 3) * 3;
            ISSUE_COPY(st, t_issue << 6);
        }
        CP_COMMIT();
        t_issue++;

        const int slot = t - (t / 3) * 3;
        const uint32_t sa = sA_u + slot * ABYTES;
        const uint32_t sb = sB_u + slot * BBYTES;
#pragma unroll
        for (int ks = 0; ks < 4; ks++) {       // 4 x k16 per 64-half tile
            uint32_t af[2][4], bf[4][2];
#pragma unroll
            for (int mt = 0; mt < 2; mt++) {
                int r = rA_l + mt * 16;
                int ch = ks * 2 + cA_l;
                uint32_t addr = sa + r * 128 + ((ch * 16) ^ ((r & 7) * 16));
                LDMX4(af[mt][0], af[mt][1], af[mt][2], af[mt][3], addr);
            }
#pragma unroll
            for (int p = 0; p < 2; p++) {
                int r = rB_l + p * 16;
                int ch = ks * 2 + cB_l;
                uint32_t addr = sb + r * 128 + ((ch * 16) ^ ((r & 7) * 16));
                LDMX4(bf[2 * p][0], bf[2 * p][1], bf[2 * p + 1][0], bf[2 * p + 1][1], addr);
            }
#pragma unroll
            for (int mt = 0; mt < 2; mt++)
#pragma unroll
                for (int nt = 0; nt < 4; nt++)
                    MMA_F16(acc[mt][nt], af[mt], bf[nt]);
        }
    }
#undef ISSUE_COPY

    if (MODE == 3) {
        const __half* hmat = (const __half*)biasv;   // H matrix [BATCH, HID], fp16
        float* kdraw = (float*)auxv;                 // [BATCH]
        const int kbase = ((bcol + wcol) >> 1) + tg; // (u,v) pair index, +nt*4
#pragma unroll
        for (int mt = 0; mt < 2; mt++) {
            int r0 = brow + wrow + mt * 16 + g;
            int b0 = r0 & (BATCH - 1);
            int b1 = (r0 + 8) & (BATCH - 1);
            float s0 = 0.f, s1 = 0.f;
#pragma unroll
            for (int nt = 0; nt < 4; nt++) {
                int kk = kbase + nt * 4;
                float h0 = __half2float(hmat[(size_t)b0 * HID + kk]);
                float h1 = __half2float(hmat[(size_t)b1 * HID + kk]);
                s0 += (1.f - h0 * h0) * acc[mt][nt][0] * acc[mt][nt][1];
                s1 += (1.f - h1 * h1) * acc[mt][nt][2] * acc[mt][nt][3];
            }
            s0 += __shfl_xor_sync(0xffffffffu, s0, 1);
            s0 += __shfl_xor_sync(0xffffffffu, s0, 2);
            s1 += __shfl_xor_sync(0xffffffffu, s1, 1);
            s1 += __shfl_xor_sync(0xffffffffu, s1, 2);
            if (tg == 0) {
                atomicAdd(&kdraw[b0], s0);
                atomicAdd(&kdraw[b1], s1);
            }
        }
        return;
    }

#pragma unroll
    for (int mt = 0; mt < 2; mt++) {
#pragma unroll
        for (int nt = 0; nt < 4; nt++) {
            int lc = wcol + nt * 8 + tg * 2;
            int r0 = brow + wrow + mt * 16 + g;
            float v0 = acc[mt][nt][0], v1 = acc[mt][nt][1];
            float v2 = acc[mt][nt][2], v3 = acc[mt][nt][3];
            if (MODE == 1) {
                __half* C = (__half*)Cv;
                float b0 = sbias[lc], b1 = sbias[lc + 1];
                __half2 h01 = __floats2half2_rn(tanhf(v0 + b0), tanhf(v1 + b1));
                __half2 h23 = __floats2half2_rn(tanhf(v2 + b0), tanhf(v3 + b1));
                *(__half2*)(C + (size_t)r0 * N + bcol + lc)       = h01;
                *(__half2*)(C + (size_t)(r0 + 8) * N + bcol + lc) = h23;
            } else {  // MODE 2
                float* C = (float*)Cv;
                float b0 = sbias[lc], b1 = sbias[lc + 1];
                v0 += b0; v1 += b1; v2 += b0; v3 += b1;
                *(float2*)(C + (size_t)r0 * N + bcol + lc)       = make_float2(v0, v1);
                *(float2*)(C + (size_t)(r0 + 8) * N + bcol + lc) = make_float2(v2, v3);
            }
        }
    }
}

// ---------------- host orchestration ----------------
extern "C" void kernel_launch(void* const* d_in, const int* in_sizes, int n_in,
                              void* d_out, int out_size) {
    (void)in_sizes; (void)n_in; (void)out_size;
    const float* x   = (const float*)d_in[0];
    const float* W1  = (const float*)d_in[1];
    const float* b1  = (const float*)d_in[2];
    const float* tw1 = (const float*)d_in[3];
    const float* W2  = (const float*)d_in[4];
    const float* b2  = (const float*)d_in[5];
    float* out = (float*)d_out;

    __half *pZIN, *pH, *pE, *pW1T, *pWIL, *pW2T;
    float *pK, *pKD;
    cudaGetSymbolAddress((void**)&pZIN, g_ZIN);
    cudaGetSymbolAddress((void**)&pH, g_H);
    cudaGetSymbolAddress((void**)&pE, g_E);
    cudaGetSymbolAddress((void**)&pW1T, g_W1T);
    cudaGetSymbolAddress((void**)&pWIL, g_WIL);
    cudaGetSymbolAddress((void**)&pW2T, g_W2T);
    cudaGetSymbolAddress((void**)&pK, g_K);
    cudaGetSymbolAddress((void**)&pKD, g_KD);

    const int SM_BIG = 1024 + 3 * (128 + 64) * 128;  // 74752
    const int SM_G2  = 1024 + 3 * (64 + 64) * 128;   // 50176
    cudaFuncSetAttribute((const void*)gemm_mma<128, 64, 1>,
                         cudaFuncAttributeMaxDynamicSharedMemorySize, SM_BIG);
    cudaFuncSetAttribute((const void*)gemm_mma<64, 64, 2>,
                         cudaFuncAttributeMaxDynamicSharedMemorySize, SM_G2);
    cudaFuncSetAttribute((const void*)gemm_mma<128, 64, 3>,
                         cudaFuncAttributeMaxDynamicSharedMemorySize, SM_BIG);

    init_kernel<<<(BATCH * DIN + 255) / 256, 256>>>(x);
    build_w1t<<<(HID * DIN + 255) / 256, 256>>>(W1);
    build_wil<<<(2 * HID * DIN + 255) / 256, 256>>>(W1, W2);
    build_w2t<<<(DIN * HID + 255) / 256, 256>>>(W2);

    // JAX threefry, partitionable semantics
    uint32_t key0 = 0u, key1 = 1234u;

    for (int step = 0; step < NSTEPS; step++) {
        uint32_t nk0, nk1;
        uint32_t sk[4][2];
        tfry(key0, key1, 0u, 0u, nk0, nk1);
        for (int s = 0; s < 4; s++)
            tfry(key0, key1, 0u, (uint32_t)(s + 1), sk[s][0], sk[s][1]);
        key0 = nk0; key1 = nk1;

        double t0d = (double)step / 9.0, t1d = (double)(step + 1) / 9.0;
        float t0 = (float)t0d;
        float dt = (float)(t1d - t0d);
        float ts[4] = {t0, t0 + dt / 3.f, t0 + 2.f * dt / 3.f, (float)t1d};

        for (int s = 0; s < 4; s++) {
            if (s == 1)      zin_kernel<<<(BATCH * DIN + 255) / 256, 256>>>(dt / 3.f, 0.f, 0.f);
            else if (s == 2) zin_kernel<<<(BATCH * DIN + 255) / 256, 256>>>(-dt / 3.f, dt, 0.f);
            else if (s == 3) zin_kernel<<<(BATCH * DIN + 255) / 256, 256>>>(dt, -dt, dt);
            // (s == 0: ZIN already holds fp16(Z))

            // H = fp16(tanh(zin @ W1 + b1 + t*tw1))    [2048x1024, K=512]
            gemm_mma<128, 64, 1><<<dim3(HID / 64, BATCH / 128), 256, SM_BIG>>>(
                pZIN, pW1T, pH, BATCH, HID, DIN, b1, (void*)tw1, ts[s]);
            // K[s] = H @ W2 + b2                       [2048x512, K=1024]
            gemm_mma<64, 64, 2><<<dim3(DIN / 64, BATCH / 64), 128, SM_G2>>>(
                pH, pW2T, pK + (size_t)s * BATCH * DIN, BATCH, DIN, HID, b2, nullptr, 0.f);

            // e keys: fk = tfry(k,(0,i)); k2 = tfry(fk,(0,1)); bits = xor-halves & 1
            uint32_t keys_e[2][2];
            for (int i = 0; i < 2; i++) {
                uint32_t f0, f1;
                tfry(sk[s][0], sk[s][1], 0u, (uint32_t)i, f0, f1);
                tfry(f0, f1, 0u, 1u, keys_e[i][0], keys_e[i][1]);
            }
            gen_e_kernel<<<dim3(BATCH * DIN / 256, 2), 256>>>(
                keys_e[0][0], keys_e[0][1], keys_e[1][0], keys_e[1][1],
                pKD + (size_t)s * BATCH);

            // fused trace GEMM + divergence reduction    [4096x2048, K=512]
            gemm_mma<128, 64, 3><<<dim3(2 * HID / 64, 2 * BATCH / 128), 256, SM_BIG>>>(
                pE, pWIL, nullptr, 2 * BATCH, 2 * HID, DIN,
                pH, pKD + (size_t)s * BATCH, 0.f);
        }
        update_step<<<(BATCH * DIN + 255) / 256, 256>>>(dt * 0.125f);
    }
    finalize_kernel<<<BATCH, 256>>>(out);
}

// round 10
// speedup vs baseline: 8.0650x; 1.2017x over previous
#include <cuda_runtime.h>
#include <cuda_fp16.h>
#include <cstdint>
#include <cstddef>

#define BATCH 2048
#define DIN   512
#define HID   1024
#define NSTEPS 9
#define CLAMPV 100.0f

// ---------------- scratch (static __device__, no allocations) ----------------
__device__ __align__(16) float  g_Z[BATCH * DIN];
__device__ __align__(16) float  g_LL[BATCH];
__device__ __align__(16) __half g_ZIN[BATCH * DIN];
__device__ __align__(16) float  g_K[4][BATCH * DIN];
__device__ __align__(16) float  g_KD[4][BATCH];                 // raw div sums (atomic)
__device__ __align__(16) __half g_H[4][(size_t)BATCH * HID];    // per-stage H buffers
__device__ __align__(16) __half g_E[(size_t)2 * BATCH * DIN];
__device__ __align__(16) __half g_W1T[(size_t)HID * DIN];       // W1^T K-major
__device__ __align__(16) __half g_WIL[(size_t)2 * HID * DIN];   // interleaved [u_k;v_k] rows
__device__ __align__(16) __half g_W2T[(size_t)DIN * HID];       // W2^T K-major

// ---------------- threefry2x32 (exact JAX implementation) ----------------
__host__ __device__ inline uint32_t rotl32(uint32_t x, int d) {
    return (x << d) | (x >> (32 - d));
}
__host__ __device__ inline void tfry(uint32_t k0, uint32_t k1,
                                     uint32_t c0, uint32_t c1,
                                     uint32_t& o0, uint32_t& o1) {
    uint32_t ks0 = k0, ks1 = k1, ks2 = k0 ^ k1 ^ 0x1BD11BDAu;
    uint32_t x0 = c0 + ks0, x1 = c1 + ks1;
#define TF_ROUND(rot) { x0 += x1; x1 = rotl32(x1, rot) ^ x0; }
    TF_ROUND(13) TF_ROUND(15) TF_ROUND(26) TF_ROUND(6)
    x0 += ks1; x1 += ks2 + 1u;
    TF_ROUND(17) TF_ROUND(29) TF_ROUND(16) TF_ROUND(24)
    x0 += ks2; x1 += ks0 + 2u;
    TF_ROUND(13) TF_ROUND(15) TF_ROUND(26) TF_ROUND(6)
    x0 += ks0; x1 += ks1 + 3u;
    TF_ROUND(17) TF_ROUND(29) TF_ROUND(16) TF_ROUND(24)
    x0 += ks1; x1 += ks2 + 4u;
    TF_ROUND(13) TF_ROUND(15) TF_ROUND(26) TF_ROUND(6)
    x0 += ks2; x1 += ks0 + 5u;
#undef TF_ROUND
    o0 = x0; o1 = x1;
}

// ---------------- helpers ----------------
#define MMA_F16(d, a, b)                                                                \
    asm volatile(                                                                       \
        "mma.sync.aligned.m16n8k16.row.col.f32.f16.f16.f32 "                            \
        "{%0,%1,%2,%3}, {%4,%5,%6,%7}, {%8,%9}, {%0,%1,%2,%3};\n"                       \
        : "+f"((d)[0]), "+f"((d)[1]), "+f"((d)[2]), "+f"((d)[3])                        \
        : "r"((a)[0]), "r"((a)[1]), "r"((a)[2]), "r"((a)[3]), "r"((b)[0]), "r"((b)[1]))

#define LDMX4(r0, r1, r2, r3, addr)                                                     \
    asm volatile("ldmatrix.sync.aligned.m8n8.x4.shared.b16 {%0,%1,%2,%3}, [%4];"        \
                 : "=r"(r0), "=r"(r1), "=r"(r2), "=r"(r3) : "r"(addr))

#define CP16(dst, src) \
    asm volatile("cp.async.cg.shared.global [%0], [%1], 16;" :: "r"(dst), "l"(src) : "memory")
#define CP_COMMIT() asm volatile("cp.async.commit_group;" ::: "memory")
#define CP_WAIT1()  asm volatile("cp.async.wait_group 1;" ::: "memory")

__device__ inline float blockReduceSum(float v) {
    __shared__ float ws[8];
    int lane = threadIdx.x & 31, w = threadIdx.x >> 5;
#pragma unroll
    for (int o = 16; o > 0; o >>= 1) v += __shfl_down_sync(0xffffffffu, v, o);
    if (lane == 0) ws[w] = v;
    __syncthreads();
    if (w == 0) {
        v = (lane < ((int)blockDim.x >> 5)) ? ws[lane] : 0.f;
#pragma unroll
        for (int o = 4; o > 0; o >>= 1) v += __shfl_down_sync(0xffffffffu, v, o);
    }
    return v;
}

// ---------------- elementwise kernels ----------------
__global__ void init_kernel(const float* __restrict__ x) {
    int i = blockIdx.x * blockDim.x + threadIdx.x;
    if (i < BATCH * DIN) { float v = x[i]; g_Z[i] = v; g_ZIN[i] = __float2half_rn(v); }
    if (i < BATCH) g_LL[i] = 0.f;
}

__global__ void build_w1t(const float* __restrict__ W1) {
    int i = blockIdx.x * blockDim.x + threadIdx.x;
    if (i >= HID * DIN) return;
    int n = i / DIN, k = i % DIN;
    g_W1T[i] = __float2half_rn(W1[(size_t)k * HID + n]);
}
// interleaved: row 2k = W1[:,k] (u), row 2k+1 = W2[k,:] (v)
__global__ void build_wil(const float* __restrict__ W1, const float* __restrict__ W2) {
    int i = blockIdx.x * blockDim.x + threadIdx.x;
    if (i >= 2 * HID * DIN) return;
    int n = i / DIN, d = i % DIN;
    int k = n >> 1;
    float v = (n & 1) ? W2[(size_t)k * DIN + d] : W1[(size_t)d * HID + k];
    g_WIL[i] = __float2half_rn(v);
}
__global__ void build_w2t(const float* __restrict__ W2) {
    int i = blockIdx.x * blockDim.x + threadIdx.x;
    if (i >= DIN * HID) return;
    int n = i / HID, k = i % HID;
    g_W2T[i] = __float2half_rn(W2[(size_t)k * DIN + n]);
}

// ZIN = fp16_round(Z + c1 K0 + c2 K1 + c3 K2)   (stages 1..3 only)
__global__ void zin_kernel(float c1, float c2, float c3) {
    int i = blockIdx.x * blockDim.x + threadIdx.x;
    if (i >= BATCH * DIN) return;
    float v = g_Z[i] + c1 * g_K[0][i] + c2 * g_K[1][i] + c3 * g_K[2][i];
    g_ZIN[i] = __float2half_rn(v);
}

// Z update + ZIN refresh + LL update (merged)
__global__ void update_step(float dt8) {
    int i = blockIdx.x * blockDim.x + threadIdx.x;
    if (i < BATCH * DIN) {
        float z = g_Z[i] + dt8 * (g_K[0][i] + 3.f * (g_K[1][i] + g_K[2][i]) + g_K[3][i]);
        g_Z[i] = z;
        g_ZIN[i] = __float2half_rn(z);
    }
    if (i < BATCH) {
        float d[4];
#pragma unroll
        for (int s = 0; s < 4; s++) {
            float v = 0.5f * g_KD[s][i];
            d[s] = fminf(fmaxf(v, -CLAMPV), CLAMPV);
        }
        g_LL[i] += dt8 * (-d[0] - 3.f * (d[1] + d[2]) - d[3]);
    }
}

// e gen + zero this stage's KD accumulator
__global__ void gen_e_kernel(uint32_t k0a, uint32_t k1a, uint32_t k0b, uint32_t k1b,
                             float* __restrict__ kdraw) {
    int i = blockIdx.x * blockDim.x + threadIdx.x;
    if (i >= BATCH * DIN) return;
    uint32_t k0 = blockIdx.y ? k0b : k0a;
    uint32_t k1 = blockIdx.y ? k1b : k1a;
    uint32_t o0, o1;
    tfry(k0, k1, 0u, (uint32_t)i, o0, o1);
    g_E[(size_t)blockIdx.y * BATCH * DIN + i] =
        ((o0 ^ o1) & 1u) ? __float2half_rn(1.f) : __float2half_rn(-1.f);
    if (blockIdx.y == 0 && i < BATCH) kdraw[i] = 0.f;
}

__global__ void finalize_kernel(float* __restrict__ out) {
    int b = blockIdx.x;
    float ssum = 0.f;
    for (int d = threadIdx.x; d < DIN; d += blockDim.x) {
        float v = g_Z[(size_t)b * DIN + d];
        out[(size_t)b * DIN + d] = v;
        ssum += v * v;
    }
    float tot = blockReduceSum(ssum);
    if (threadIdx.x == 0) out[(size_t)BATCH * DIN + b] = -0.5f * tot + g_LL[b];
}

// ---------------- fp16 mma.sync GEMM, cp.async 3-stage pipeline ----------------
// C[M,N] = A[M,K] @ Brows[N,K]^T, fp16 operands, fp32 accumulate.
// MODE 1: H[half] = fp16(tanh(acc+bias+tval*tvec))   MODE 2: C[float] = acc+bias
// MODE 3: no store; B cols (u,v)-interleaved; kdraw[b] += sum_k (1-h^2) u v
template <int BM, int BN, int MODE>
__global__ __launch_bounds__((BM / 32) * (BN / 32) * 32, 512 / ((BM / 32) * (BN / 32) * 32))
void gemm_mma(const __half* __restrict__ A, const __half* __restrict__ B,
              void* __restrict__ Cv, int M, int N, int K,
              const void* __restrict__ biasv, void* __restrict__ auxv, float tval) {
    extern __shared__ __align__(16) char smem[];
    constexpr int THREADS = (BM / 32) * (BN / 32) * 32;
    constexpr int WCOLS = BN / 32;
    constexpr int A16 = BM * 8 / THREADS;
    constexpr int B16 = BN * 8 / THREADS;
    constexpr int ABYTES = BM * 128;
    constexpr int BBYTES = BN * 128;

    float* sbias = (float*)smem;
    const uint32_t sA_u = (uint32_t)__cvta_generic_to_shared(smem + 1024);
    const uint32_t sB_u = sA_u + 3 * ABYTES;

    const int tid = threadIdx.x;
    const int lane = tid & 31;
    const int warp = tid >> 5;
    const int g = lane >> 2;
    const int tg = lane & 3;
    const int wrow = (warp / WCOLS) * 32;
    const int wcol = (warp % WCOLS) * 32;
    const int brow = blockIdx.y * BM;
    const int bcol = blockIdx.x * BN;

    if (MODE == 1 && tid < BN) {
        const float* bias = (const float*)biasv;
        const float* tvec = (const float*)auxv;
        sbias[tid] = bias[bcol + tid] + tval * tvec[bcol + tid];
    }
    if (MODE == 2 && tid < BN) sbias[tid] = ((const float*)biasv)[bcol + tid];

    float acc[2][4][4];
#pragma unroll
    for (int i = 0; i < 2; i++)
#pragma unroll
        for (int j = 0; j < 4; j++)
#pragma unroll
            for (int q = 0; q < 4; q++) acc[i][j][q] = 0.f;

    const int rA_l = wrow + (lane & 15);
    const int cA_l = lane >> 4;
    const int rB_l = wcol + ((lane >> 4) * 8) + (lane & 7);
    const int cB_l = (lane >> 3) & 1;

    const int nk = K >> 6;   // 64 halves per k-tile

#define ISSUE_COPY(st, kt)                                                              \
    do {                                                                                \
        _Pragma("unroll")                                                               \
        for (int i = 0; i < A16; i++) {                                                 \
            int f = tid + i * THREADS; int r = f >> 3, seg = f & 7;                     \
            uint32_t dst = sA_u + (st) * ABYTES + r * 128 + ((seg * 16) ^ ((r & 7) * 16)); \
            CP16(dst, A + (size_t)(brow + r) * K + (kt) + seg * 8);                     \
        }                                                                               \
        _Pragma("unroll")                                                               \
        for (int i = 0; i < B16; i++) {                                                 \
            int f = tid + i * THREADS; int r = f >> 3, seg = f & 7;                     \
            uint32_t dst = sB_u + (st) * BBYTES + r * 128 + ((seg * 16) ^ ((r & 7) * 16)); \
            CP16(dst, B + (size_t)(bcol + r) * K + (kt) + seg * 8);                     \
        }                                                                               \
    } while (0)

    ISSUE_COPY(0, 0);
    CP_COMMIT();
    if (1 < nk) ISSUE_COPY(1, 64);
    CP_COMMIT();

    int t_issue = 2;
    for (int t = 0; t < nk; t++) {
        CP_WAIT1();
        __syncthreads();
        if (t_issue < nk) {
            int st = t_issue - (t_issue / 3) * 3;
            ISSUE_COPY(st, t_issue << 6);
        }
        CP_COMMIT();
        t_issue++;

        const int slot = t - (t / 3) * 3;
        const uint32_t sa = sA_u + slot * ABYTES;
        const uint32_t sb = sB_u + slot * BBYTES;
#pragma unroll
        for (int ks = 0; ks < 4; ks++) {
            uint32_t af[2][4], bf[4][2];
#pragma unroll
            for (int mt = 0; mt < 2; mt++) {
                int r = rA_l + mt * 16;
                int ch = ks * 2 + cA_l;
                uint32_t addr = sa + r * 128 + ((ch * 16) ^ ((r & 7) * 16));
                LDMX4(af[mt][0], af[mt][1], af[mt][2], af[mt][3], addr);
            }
#pragma unroll
            for (int p = 0; p < 2; p++) {
                int r = rB_l + p * 16;
                int ch = ks * 2 + cB_l;
                uint32_t addr = sb + r * 128 + ((ch * 16) ^ ((r & 7) * 16));
                LDMX4(bf[2 * p][0], bf[2 * p][1], bf[2 * p + 1][0], bf[2 * p + 1][1], addr);
            }
#pragma unroll
            for (int mt = 0; mt < 2; mt++)
#pragma unroll
                for (int nt = 0; nt < 4; nt++)
                    MMA_F16(acc[mt][nt], af[mt], bf[nt]);
        }
    }
#undef ISSUE_COPY

    if (MODE == 3) {
        const __half* hmat = (const __half*)biasv;   // H matrix [BATCH, HID], fp16
        float* kdraw = (float*)auxv;                 // [BATCH]
        const int kbase = ((bcol + wcol) >> 1) + tg;
#pragma unroll
        for (int mt = 0; mt < 2; mt++) {
            int r0 = brow + wrow + mt * 16 + g;
            int b0 = r0 & (BATCH - 1);
            int b1 = (r0 + 8) & (BATCH - 1);
            float s0 = 0.f, s1 = 0.f;
#pragma unroll
            for (int nt = 0; nt < 4; nt++) {
                int kk = kbase + nt * 4;
                float h0 = __half2float(hmat[(size_t)b0 * HID + kk]);
                float h1 = __half2float(hmat[(size_t)b1 * HID + kk]);
                s0 += (1.f - h0 * h0) * acc[mt][nt][0] * acc[mt][nt][1];
                s1 += (1.f - h1 * h1) * acc[mt][nt][2] * acc[mt][nt][3];
            }
            s0 += __shfl_xor_sync(0xffffffffu, s0, 1);
            s0 += __shfl_xor_sync(0xffffffffu, s0, 2);
            s1 += __shfl_xor_sync(0xffffffffu, s1, 1);
            s1 += __shfl_xor_sync(0xffffffffu, s1, 2);
            if (tg == 0) {
                atomicAdd(&kdraw[b0], s0);
                atomicAdd(&kdraw[b1], s1);
            }
        }
        return;
    }

#pragma unroll
    for (int mt = 0; mt < 2; mt++) {
#pragma unroll
        for (int nt = 0; nt < 4; nt++) {
            int lc = wcol + nt * 8 + tg * 2;
            int r0 = brow + wrow + mt * 16 + g;
            float v0 = acc[mt][nt][0], v1 = acc[mt][nt][1];
            float v2 = acc[mt][nt][2], v3 = acc[mt][nt][3];
            if (MODE == 1) {
                __half* C = (__half*)Cv;
                float b0 = sbias[lc], b1 = sbias[lc + 1];
                __half2 h01 = __floats2half2_rn(tanhf(v0 + b0), tanhf(v1 + b1));
                __half2 h23 = __floats2half2_rn(tanhf(v2 + b0), tanhf(v3 + b1));
                *(__half2*)(C + (size_t)r0 * N + bcol + lc)       = h01;
                *(__half2*)(C + (size_t)(r0 + 8) * N + bcol + lc) = h23;
            } else {  // MODE 2
                float* C = (float*)Cv;
                float b0 = sbias[lc], b1 = sbias[lc + 1];
                v0 += b0; v1 += b1; v2 += b0; v3 += b1;
                *(float2*)(C + (size_t)r0 * N + bcol + lc)       = make_float2(v0, v1);
                *(float2*)(C + (size_t)(r0 + 8) * N + bcol + lc) = make_float2(v2, v3);
            }
        }
    }
}

// ---------------- host orchestration ----------------
extern "C" void kernel_launch(void* const* d_in, const int* in_sizes, int n_in,
                              void* d_out, int out_size) {
    (void)in_sizes; (void)n_in; (void)out_size;
    const float* x   = (const float*)d_in[0];
    const float* W1  = (const float*)d_in[1];
    const float* b1  = (const float*)d_in[2];
    const float* tw1 = (const float*)d_in[3];
    const float* W2  = (const float*)d_in[4];
    const float* b2  = (const float*)d_in[5];
    float* out = (float*)d_out;

    __half *pZIN, *pH, *pE, *pW1T, *pWIL, *pW2T;
    float *pK, *pKD;
    cudaGetSymbolAddress((void**)&pZIN, g_ZIN);
    cudaGetSymbolAddress((void**)&pH, g_H);
    cudaGetSymbolAddress((void**)&pE, g_E);
    cudaGetSymbolAddress((void**)&pW1T, g_W1T);
    cudaGetSymbolAddress((void**)&pWIL, g_WIL);
    cudaGetSymbolAddress((void**)&pW2T, g_W2T);
    cudaGetSymbolAddress((void**)&pK, g_K);
    cudaGetSymbolAddress((void**)&pKD, g_KD);

    // side stream + fork-join events (created once; host resources, no device mem)
    static cudaStream_t sS = nullptr;
    static cudaEvent_t evRoot = nullptr, evG1 = nullptr, evJ = nullptr, evU = nullptr;
    if (!sS) {
        cudaStreamCreateWithFlags(&sS, cudaStreamNonBlocking);
        cudaEventCreateWithFlags(&evRoot, cudaEventDisableTiming);
        cudaEventCreateWithFlags(&evG1, cudaEventDisableTiming);
        cudaEventCreateWithFlags(&evJ, cudaEventDisableTiming);
        cudaEventCreateWithFlags(&evU, cudaEventDisableTiming);
    }

    const int SM_BIG = 1024 + 3 * (128 + 64) * 128;  // 74752
    const int SM_G2  = 1024 + 3 * (64 + 64) * 128;   // 50176
    cudaFuncSetAttribute((const void*)gemm_mma<128, 64, 1>,
                         cudaFuncAttributeMaxDynamicSharedMemorySize, SM_BIG);
    cudaFuncSetAttribute((const void*)gemm_mma<64, 64, 2>,
                         cudaFuncAttributeMaxDynamicSharedMemorySize, SM_G2);
    cudaFuncSetAttribute((const void*)gemm_mma<128, 64, 3>,
                         cudaFuncAttributeMaxDynamicSharedMemorySize, SM_BIG);

    init_kernel<<<(BATCH * DIN + 255) / 256, 256>>>(x);
    build_w1t<<<(HID * DIN + 255) / 256, 256>>>(W1);
    build_wil<<<(2 * HID * DIN + 255) / 256, 256>>>(W1, W2);
    build_w2t<<<(DIN * HID + 255) / 256, 256>>>(W2);
    cudaEventRecord(evRoot, 0);

    // JAX threefry, partitionable semantics
    uint32_t key0 = 0u, key1 = 1234u;

    for (int step = 0; step < NSTEPS; step++) {
        uint32_t nk0, nk1;
        uint32_t sk[4][2];
        tfry(key0, key1, 0u, 0u, nk0, nk1);
        for (int s = 0; s < 4; s++)
            tfry(key0, key1, 0u, (uint32_t)(s + 1), sk[s][0], sk[s][1]);
        key0 = nk0; key1 = nk1;

        double t0d = (double)step / 9.0, t1d = (double)(step + 1) / 9.0;
        float t0 = (float)t0d;
        float dt = (float)(t1d - t0d);
        float ts[4] = {t0, t0 + dt / 3.f, t0 + 2.f * dt / 3.f, (float)t1d};

        for (int s = 0; s < 4; s++) {
            __half* Hs = pH + (size_t)s * BATCH * HID;

            // ---- main stream: integrator chain ----
            if (s == 1)      zin_kernel<<<(BATCH * DIN + 255) / 256, 256>>>(dt / 3.f, 0.f, 0.f);
            else if (s == 2) zin_kernel<<<(BATCH * DIN + 255) / 256, 256>>>(-dt / 3.f, dt, 0.f);
            else if (s == 3) zin_kernel<<<(BATCH * DIN + 255) / 256, 256>>>(dt, -dt, dt);
            // (s == 0: ZIN already holds fp16(Z))

            // H[s] = fp16(tanh(zin @ W1 + b1 + t*tw1))   [2048x1024, K=512]
            gemm_mma<128, 64, 1><<<dim3(HID / 64, BATCH / 128), 256, SM_BIG>>>(
                pZIN, pW1T, Hs, BATCH, HID, DIN, b1, (void*)tw1, ts[s]);
            cudaEventRecord(evG1, 0);
            // K[s] = H[s] @ W2 + b2                      [2048x512, K=1024]
            gemm_mma<64, 64, 2><<<dim3(DIN / 64, BATCH / 64), 128, SM_G2>>>(
                Hs, pW2T, pK + (size_t)s * BATCH * DIN, BATCH, DIN, HID, b2, nullptr, 0.f);

            // ---- side stream: trace chain ----
            if (s == 0) cudaStreamWaitEvent(sS, (step == 0) ? evRoot : evU, 0);

            uint32_t keys_e[2][2];
            for (int i = 0; i < 2; i++) {
                uint32_t f0, f1;
                tfry(sk[s][0], sk[s][1], 0u, (uint32_t)i, f0, f1);
                tfry(f0, f1, 0u, 1u, keys_e[i][0], keys_e[i][1]);
            }
            gen_e_kernel<<<dim3(BATCH * DIN / 256, 2), 256, 0, sS>>>(
                keys_e[0][0], keys_e[0][1], keys_e[1][0], keys_e[1][1],
                pKD + (size_t)s * BATCH);
            cudaStreamWaitEvent(sS, evG1, 0);
            // fused trace GEMM + divergence reduction     [4096x2048, K=512]
            gemm_mma<128, 64, 3><<<dim3(2 * HID / 64, 2 * BATCH / 128), 256, SM_BIG, sS>>>(
                pE, pWIL, nullptr, 2 * BATCH, 2 * HID, DIN,
                Hs, pKD + (size_t)s * BATCH, 0.f);
        }
        // join: update needs all KD (side) and K (main)
        cudaEventRecord(evJ, sS);
        cudaStreamWaitEvent(0, evJ, 0);
        update_step<<<(BATCH * DIN + 255) / 256, 256>>>(dt * 0.125f);
        cudaEventRecord(evU, 0);
    }
    finalize_kernel<<<BATCH, 256>>>(out);
}